// round 8
// baseline (speedup 1.0000x reference)
#include <cuda_runtime.h>
#include <cstdint>
#include <math.h>

constexpr int B  = 16;
constexpr int C  = 256;
constexpr int HW = 4096;
constexpr int D  = 32;

__device__ float g_q[B * HW * D];   // [b][n][d]  fp32
__device__ float g_k[B * HW * D];   // [b][m][d]  fp32
__device__ float g_v[B * HW * C];   // [b][e][tile][k-interleaved]  tf32-rounded

// cvt.rna.tf32.f32: destination is a .b32 register (tf32 bit pattern).
__device__ __forceinline__ uint32_t to_tf32_bits(float x) {
    uint32_t r;
    asm("cvt.rna.tf32.f32 %0, %1;" : "=r"(r) : "f"(x));
    return r;
}

// tf32 mma: A/B fragments are .b32 regs, C/D are .f32
__device__ __forceinline__ void mma_tf32_16x8x8(
    float& c0, float& c1, float& c2, float& c3,
    uint32_t a0, uint32_t a1, uint32_t a2, uint32_t a3,
    uint32_t b0, uint32_t b1)
{
    asm volatile(
        "mma.sync.aligned.m16n8k8.row.col.f32.tf32.tf32.f32 "
        "{%0,%1,%2,%3}, {%4,%5,%6,%7}, {%8,%9}, {%0,%1,%2,%3};"
        : "+f"(c0), "+f"(c1), "+f"(c2), "+f"(c3)
        : "r"(a0), "r"(a1), "r"(a2), "r"(a3), "r"(b0), "r"(b1));
}

// k-interleave within a 32-k tile: pairs (k, k+4) adjacent for float2 frag loads
__device__ __forceinline__ int kperm(int k) {
    return ((k & 3) << 3) + ((k >> 3) << 1) + ((k >> 2) & 1);
}

// ===========================================================================
// Projection GEMMs: out[b][n][e] = sum_c W[e][c] * x[b][c][n]
// ===========================================================================
__global__ __launch_bounds__(256) void proj_kernel(
    const float* __restrict__ x, const float* __restrict__ W,
    float* __restrict__ out, int Etot)
{
    constexpr int BN = 128, KC = 32;
    __shared__ __align__(16) float Xs[KC][BN + 4];
    __shared__ float Ws[KC][33];
    const int b = blockIdx.y, n0 = blockIdx.x * BN, e0 = blockIdx.z * 32;
    const int tid = threadIdx.x, tn = tid & 31, te = tid >> 5;
    float acc[4][4] = {};
    const float* xb = x + (size_t)b * C * HW;
    for (int c0 = 0; c0 < C; c0 += KC) {
        #pragma unroll
        for (int r = 0; r < 4; r++) {
            int idx = tid + 256 * r;
            int c = idx >> 5, n4 = (idx & 31) * 4;
            *(float4*)&Xs[c][n4] = *(const float4*)&xb[(size_t)(c0 + c) * HW + n0 + n4];
        }
        {
            int e = tid >> 3, c4 = (tid & 7) * 4;
            float4 w4 = *(const float4*)&W[(size_t)(e0 + e) * C + c0 + c4];
            Ws[c4 + 0][e] = w4.x; Ws[c4 + 1][e] = w4.y;
            Ws[c4 + 2][e] = w4.z; Ws[c4 + 3][e] = w4.w;
        }
        __syncthreads();
        #pragma unroll
        for (int c = 0; c < KC; c++) {
            float4 xa = *(const float4*)&Xs[c][tn * 4];
            float xv[4] = {xa.x, xa.y, xa.z, xa.w};
            float wb[4];
            #pragma unroll
            for (int j = 0; j < 4; j++) wb[j] = Ws[c][te * 4 + j];
            #pragma unroll
            for (int i = 0; i < 4; i++)
                #pragma unroll
                for (int j = 0; j < 4; j++)
                    acc[i][j] = fmaf(xv[i], wb[j], acc[i][j]);
        }
        __syncthreads();
    }
    #pragma unroll
    for (int i = 0; i < 4; i++) {
        float4 o4 = make_float4(acc[i][0], acc[i][1], acc[i][2], acc[i][3]);
        int n = n0 + tn * 4 + i;
        *(float4*)&out[((size_t)b * HW + n) * Etot + e0 + te * 4] = o4;
    }
}

// V projection: transposed + tf32-rounded + k-interleaved store:
//   g_v[(b*C+e)*HW + (n/32)*32 + kperm(n%32)]
__global__ __launch_bounds__(256) void proj_kernel_T(
    const float* __restrict__ x, const float* __restrict__ W,
    float* __restrict__ out, int Etot)
{
    constexpr int BN = 128, KC = 32;
    __shared__ __align__(16) float Xs[KC][BN + 4];
    __shared__ float Ws[KC][33];
    const int b = blockIdx.y, n0 = blockIdx.x * BN, e0 = blockIdx.z * 32;
    const int tid = threadIdx.x, tn = tid & 31, te = tid >> 5;
    float acc[4][4] = {};
    const float* xb = x + (size_t)b * C * HW;
    for (int c0 = 0; c0 < C; c0 += KC) {
        #pragma unroll
        for (int r = 0; r < 4; r++) {
            int idx = tid + 256 * r;
            int c = idx >> 5, n4 = (idx & 31) * 4;
            *(float4*)&Xs[c][n4] = *(const float4*)&xb[(size_t)(c0 + c) * HW + n0 + n4];
        }
        {
            int e = tid >> 3, c4 = (tid & 7) * 4;
            float4 w4 = *(const float4*)&W[(size_t)(e0 + e) * C + c0 + c4];
            Ws[c4 + 0][e] = w4.x; Ws[c4 + 1][e] = w4.y;
            Ws[c4 + 2][e] = w4.z; Ws[c4 + 3][e] = w4.w;
        }
        __syncthreads();
        #pragma unroll
        for (int c = 0; c < KC; c++) {
            float4 xa = *(const float4*)&Xs[c][tn * 4];
            float xv[4] = {xa.x, xa.y, xa.z, xa.w};
            float wb[4];
            #pragma unroll
            for (int j = 0; j < 4; j++) wb[j] = Ws[c][te * 4 + j];
            #pragma unroll
            for (int i = 0; i < 4; i++)
                #pragma unroll
                for (int j = 0; j < 4; j++)
                    acc[i][j] = fmaf(xv[i], wb[j], acc[i][j]);
        }
        __syncthreads();
    }
    #pragma unroll
    for (int j = 0; j < 4; j++) {
        int e = e0 + te * 4 + j;
        #pragma unroll
        for (int i = 0; i < 4; i++) {
            int n = n0 + tn * 4 + i;
            int t = n >> 5, k = n & 31;
            out[((size_t)b * Etot + e) * HW + t * 32 + kperm(k)] =
                __uint_as_float(to_tf32_bits(acc[i][j]));
        }
    }
}

// ===========================================================================
// Flash attention: fp32 S on FFMA, tf32 mma.sync P*V.
// CTA: 64 m x 256 e. 8 warps; MMA warp tile = 32m x 64e (2 m16 x 8 n8).
// P/V staged in k-interleaved smem (stride 34 -> conflict-free LDS.64 frags).
// ===========================================================================
constexpr int MT = 64;
constexpr int NT = 32;
constexpr int NTILES = HW / NT;   // 128

constexpr int ST_PV = 34;    // Ps/Vs row stride (floats)
constexpr int ST_STG = 130;  // epilogue stage stride

// smem float offsets (all even -> float2-aligned)
constexpr int QS_OFF  = 0;                     // [64][32]   = 2048
constexpr int KS_OFF  = QS_OFF + 64 * 32;      // [32][36]   = 1152
constexpr int PS_OFF  = KS_OFF + 32 * 36;      // [64][34]   = 2176
constexpr int INV_OFF = PS_OFF + 64 * ST_PV;   // [64]
constexpr int VS_OFF  = INV_OFF + 64;          // [256][34]  = 8704 (also Stage [64][130]=8320)
constexpr int FLASH_FLOATS = VS_OFF + 256 * ST_PV;
constexpr int FLASH_SMEM = FLASH_FLOATS * 4;   // 56576 B

__global__ __launch_bounds__(256, 2) void flash_kernel(
    const float* __restrict__ x, const float* __restrict__ gamma_p,
    float* __restrict__ out)
{
    extern __shared__ __align__(16) float sm[];
    float* Qs    = sm + QS_OFF;
    float* Ks    = sm + KS_OFF;
    float* Ps    = sm + PS_OFF;
    float* invs  = sm + INV_OFF;
    float* Vs    = sm + VS_OFF;
    float* Stage = sm + VS_OFF;   // reused in epilogue

    const int tid  = threadIdx.x;
    const int wid  = tid >> 5;
    const int lane = tid & 31;
    const int b    = blockIdx.y;
    const int m0   = blockIdx.x * MT;

    // Resident K-block (attention "queries"): Qs[m][d], m in [0,64)
    #pragma unroll
    for (int r = 0; r < 2; r++) {
        int idx = tid + 256 * r;
        int m = idx >> 3, d4 = (idx & 7) * 4;
        *(float4*)&Qs[m * 32 + d4] =
            *(const float4*)&g_k[((size_t)b * HW + m0 + m) * D + d4];
    }

    const int tm = wid;              // S-phase: warp owns rows tm*8..tm*8+7
    const int g  = lane >> 2;        // mma groupID (row within m16 / e-row within n8)
    const int tg = lane & 3;         // mma thread-in-group (k index)
    const int pm = (wid & 1) * 32;   // mma m-block base (32 m per warp)
    const int pe = (wid >> 1) * 64;  // mma e-block base (64 e per warp)

    float acc[2][8][4] = {};
    float rsum[8] = {};

    const int ldn  = tid >> 3;          // Ks row / Vs e-base
    const int ldd4 = (tid & 7) * 4;     // 4-float chunk
    const int fl   = ((lane & 3) << 3) + ((lane >> 3) << 1) + ((lane >> 2) & 1);

    for (int t = 0; t < NTILES; t++) {
        const int n0 = t * NT;
        // Ks: q rows [n0, n0+32), fp32 exact
        *(float4*)&Ks[ldn * 36 + ldd4] =
            *(const float4*)&g_q[((size_t)b * HW + n0 + ldn) * D + ldd4];
        // Vs: copy interleaved 32-float blocks (8 passes of 32 e-rows)
        {
            const float* vp = &g_v[((size_t)b * C + ldn) * HW + n0 + ldd4];
            #pragma unroll
            for (int p = 0; p < 8; p++) {
                float4 v4 = *(const float4*)(vp + (size_t)(32 * p) * HW);
                float2* dst = (float2*)&Vs[(ldn + 32 * p) * ST_PV + ldd4];
                dst[0] = make_float2(v4.x, v4.y);
                dst[1] = make_float2(v4.z, v4.w);
            }
        }
        __syncthreads();

        // S phase: s[i] = dot(Qs[tm*8+i], Ks[lane]) in fp32
        float s[8] = {};
        #pragma unroll
        for (int d4 = 0; d4 < 8; d4++) {
            float4 kv = *(const float4*)&Ks[lane * 36 + d4 * 4];
            #pragma unroll
            for (int i = 0; i < 8; i++) {
                float4 qv = *(const float4*)&Qs[(tm * 8 + i) * 32 + d4 * 4];
                s[i] = fmaf(qv.x, kv.x, s[i]);
                s[i] = fmaf(qv.y, kv.y, s[i]);
                s[i] = fmaf(qv.z, kv.z, s[i]);
                s[i] = fmaf(qv.w, kv.w, s[i]);
            }
        }
        // p = exp(s) (no-max: |s| << 88), tf32-round, store k-interleaved
        #pragma unroll
        for (int i = 0; i < 8; i++) {
            float pt = __uint_as_float(to_tf32_bits(__expf(s[i])));
            rsum[i] += pt;
            Ps[(tm * 8 + i) * ST_PV + fl] = pt;
        }
        __syncthreads();

        // MMA phase: acc[32m x 64e] += P[32m x 32k] * V[32k x 64e]
        #pragma unroll
        for (int kk = 0; kk < 4; kk++) {
            const int fo = 8 * tg + 2 * kk;
            float2 aA[2][2];
            #pragma unroll
            for (int mb = 0; mb < 2; mb++) {
                aA[mb][0] = *(const float2*)&Ps[(pm + mb * 16 + g) * ST_PV + fo];
                aA[mb][1] = *(const float2*)&Ps[(pm + mb * 16 + g + 8) * ST_PV + fo];
            }
            #pragma unroll
            for (int nb = 0; nb < 8; nb++) {
                float2 bb = *(const float2*)&Vs[(pe + nb * 8 + g) * ST_PV + fo];
                uint32_t b0 = __float_as_uint(bb.x);
                uint32_t b1 = __float_as_uint(bb.y);
                #pragma unroll
                for (int mb = 0; mb < 2; mb++) {
                    mma_tf32_16x8x8(acc[mb][nb][0], acc[mb][nb][1],
                                    acc[mb][nb][2], acc[mb][nb][3],
                                    __float_as_uint(aA[mb][0].x),
                                    __float_as_uint(aA[mb][1].x),
                                    __float_as_uint(aA[mb][0].y),
                                    __float_as_uint(aA[mb][1].y),
                                    b0, b1);
                }
            }
        }
        __syncthreads();
    }

    // Row-sum reduction -> invs[m] = gamma / rsum[m]
    const float gamma = *gamma_p;
    #pragma unroll
    for (int i = 0; i < 8; i++) {
        float tsum = rsum[i];
        #pragma unroll
        for (int off = 16; off > 0; off >>= 1)
            tsum += __shfl_xor_sync(0xffffffffu, tsum, off);
        if (lane == 0) invs[tm * 8 + i] = gamma / tsum;
    }
    __syncthreads();

    // Epilogue: two e-halves staged [64][130], coalesced residual-add stores.
    const int ml  = (lane & 15) * 4;
    const int sub = lane >> 4;
    #pragma unroll
    for (int half = 0; half < 2; half++) {
        if ((wid >> 2) == half) {
            const int pe_loc = ((wid >> 1) & 1) * 64;
            #pragma unroll
            for (int mb = 0; mb < 2; mb++) {
                const int r0 = pm + mb * 16 + g;
                const int r1 = r0 + 8;
                const float i0 = invs[r0];
                const float i1 = invs[r1];
                #pragma unroll
                for (int nb = 0; nb < 8; nb++) {
                    int col = pe_loc + nb * 8 + tg * 2;
                    *(float2*)&Stage[r0 * ST_STG + col] =
                        make_float2(acc[mb][nb][0] * i0, acc[mb][nb][1] * i0);
                    *(float2*)&Stage[r1 * ST_STG + col] =
                        make_float2(acc[mb][nb][2] * i1, acc[mb][nb][3] * i1);
                }
            }
        }
        __syncthreads();
        #pragma unroll
        for (int it = 0; it < 8; it++) {
            int e_loc = it * 16 + wid * 2 + sub;
            int eg = half * 128 + e_loc;
            size_t idx = ((size_t)b * C + eg) * HW + m0 + ml;
            float4 xv = *(const float4*)&x[idx];
            float4 ov;
            ov.x = Stage[(ml + 0) * ST_STG + e_loc] + xv.x;
            ov.y = Stage[(ml + 1) * ST_STG + e_loc] + xv.y;
            ov.z = Stage[(ml + 2) * ST_STG + e_loc] + xv.z;
            ov.w = Stage[(ml + 3) * ST_STG + e_loc] + xv.w;
            *(float4*)&out[idx] = ov;
        }
        __syncthreads();
    }
}

// ===========================================================================
extern "C" void kernel_launch(void* const* d_in, const int* in_sizes, int n_in,
                              void* d_out, int out_size)
{
    const float* x     = (const float*)d_in[0];
    const float* Wq    = (const float*)d_in[1];
    const float* Wk    = (const float*)d_in[2];
    const float* Wv    = (const float*)d_in[3];
    const float* gamma = (const float*)d_in[4];
    float* out = (float*)d_out;

    void *qp, *kp, *vp;
    cudaGetSymbolAddress(&qp, g_q);
    cudaGetSymbolAddress(&kp, g_k);
    cudaGetSymbolAddress(&vp, g_v);

    static bool attr_set = false;
    if (!attr_set) {
        cudaFuncSetAttribute(flash_kernel,
                             cudaFuncAttributeMaxDynamicSharedMemorySize,
                             FLASH_SMEM);
        attr_set = true;
    }

    dim3 blk(256);
    proj_kernel  <<<dim3(HW / 128, B, 1), blk>>>(x, Wq, (float*)qp, D);
    proj_kernel  <<<dim3(HW / 128, B, 1), blk>>>(x, Wk, (float*)kp, D);
    proj_kernel_T<<<dim3(HW / 128, B, 8), blk>>>(x, Wv, (float*)vp, C);
    flash_kernel<<<dim3(HW / MT, B), blk, FLASH_SMEM>>>(x, gamma, out);
}

// round 10
// speedup vs baseline: 1.0319x; 1.0319x over previous
#include <cuda_runtime.h>
#include <cstdint>
#include <math.h>

constexpr int B  = 16;
constexpr int C  = 256;
constexpr int HW = 4096;
constexpr int D  = 32;

__device__ float g_q[B * HW * D];   // [b][n][d]  fp32
__device__ float g_k[B * HW * D];   // [b][m][d]  fp32
__device__ float g_v[B * HW * C];   // [b][e][tile][k-interleaved]  tf32-rounded

// cvt.rna.tf32.f32: destination is a .b32 register (tf32 bit pattern).
__device__ __forceinline__ uint32_t to_tf32_bits(float x) {
    uint32_t r;
    asm("cvt.rna.tf32.f32 %0, %1;" : "=r"(r) : "f"(x));
    return r;
}

// tf32 mma: A/B fragments are .b32 regs, C/D are .f32
__device__ __forceinline__ void mma_tf32_16x8x8(
    float& c0, float& c1, float& c2, float& c3,
    uint32_t a0, uint32_t a1, uint32_t a2, uint32_t a3,
    uint32_t b0, uint32_t b1)
{
    asm volatile(
        "mma.sync.aligned.m16n8k8.row.col.f32.tf32.tf32.f32 "
        "{%0,%1,%2,%3}, {%4,%5,%6,%7}, {%8,%9}, {%0,%1,%2,%3};"
        : "+f"(c0), "+f"(c1), "+f"(c2), "+f"(c3)
        : "r"(a0), "r"(a1), "r"(a2), "r"(a3), "r"(b0), "r"(b1));
}

// k-interleave within a 32-k tile (pairs (k, k+4) adjacent) and its inverse.
__device__ __forceinline__ int kperm(int k) {
    return ((k & 3) << 3) + ((k >> 3) << 1) + ((k >> 2) & 1);
}
__device__ __forceinline__ int kinv(int d) {
    return (d >> 3) + ((d & 1) << 2) + (((d >> 1) & 3) << 3);
}

// ===========================================================================
// Projection GEMMs: out[b][n][e] = sum_c W[e][c] * x[b][c][n]
// ===========================================================================
__global__ __launch_bounds__(256) void proj_kernel(
    const float* __restrict__ x, const float* __restrict__ W,
    float* __restrict__ out, int Etot)
{
    constexpr int BN = 128, KC = 32;
    __shared__ __align__(16) float Xs[KC][BN + 4];
    __shared__ float Ws[KC][33];
    const int b = blockIdx.y, n0 = blockIdx.x * BN, e0 = blockIdx.z * 32;
    const int tid = threadIdx.x, tn = tid & 31, te = tid >> 5;
    float acc[4][4] = {};
    const float* xb = x + (size_t)b * C * HW;
    for (int c0 = 0; c0 < C; c0 += KC) {
        #pragma unroll
        for (int r = 0; r < 4; r++) {
            int idx = tid + 256 * r;
            int c = idx >> 5, n4 = (idx & 31) * 4;
            *(float4*)&Xs[c][n4] = *(const float4*)&xb[(size_t)(c0 + c) * HW + n0 + n4];
        }
        {
            int e = tid >> 3, c4 = (tid & 7) * 4;
            float4 w4 = *(const float4*)&W[(size_t)(e0 + e) * C + c0 + c4];
            Ws[c4 + 0][e] = w4.x; Ws[c4 + 1][e] = w4.y;
            Ws[c4 + 2][e] = w4.z; Ws[c4 + 3][e] = w4.w;
        }
        __syncthreads();
        #pragma unroll
        for (int c = 0; c < KC; c++) {
            float4 xa = *(const float4*)&Xs[c][tn * 4];
            float xv[4] = {xa.x, xa.y, xa.z, xa.w};
            float wb[4];
            #pragma unroll
            for (int j = 0; j < 4; j++) wb[j] = Ws[c][te * 4 + j];
            #pragma unroll
            for (int i = 0; i < 4; i++)
                #pragma unroll
                for (int j = 0; j < 4; j++)
                    acc[i][j] = fmaf(xv[i], wb[j], acc[i][j]);
        }
        __syncthreads();
    }
    #pragma unroll
    for (int i = 0; i < 4; i++) {
        float4 o4 = make_float4(acc[i][0], acc[i][1], acc[i][2], acc[i][3]);
        int n = n0 + tn * 4 + i;
        *(float4*)&out[((size_t)b * HW + n) * Etot + e0 + te * 4] = o4;
    }
}

// V projection: transposed + tf32-rounded + k-interleaved, with smem-staged
// COALESCED float4 stores.
__global__ __launch_bounds__(256) void proj_kernel_T(
    const float* __restrict__ x, const float* __restrict__ W,
    float* __restrict__ out, int Etot)
{
    constexpr int BN = 128, KC = 32;
    __shared__ __align__(16) float Xs[KC][BN + 4];
    __shared__ float Ws[KC][33];
    const int b = blockIdx.y, n0 = blockIdx.x * BN, e0 = blockIdx.z * 32;
    const int tid = threadIdx.x, tn = tid & 31, te = tid >> 5;
    float acc[4][4] = {};
    const float* xb = x + (size_t)b * C * HW;
    for (int c0 = 0; c0 < C; c0 += KC) {
        #pragma unroll
        for (int r = 0; r < 4; r++) {
            int idx = tid + 256 * r;
            int c = idx >> 5, n4 = (idx & 31) * 4;
            *(float4*)&Xs[c][n4] = *(const float4*)&xb[(size_t)(c0 + c) * HW + n0 + n4];
        }
        {
            int e = tid >> 3, c4 = (tid & 7) * 4;
            float4 w4 = *(const float4*)&W[(size_t)(e0 + e) * C + c0 + c4];
            Ws[c4 + 0][e] = w4.x; Ws[c4 + 1][e] = w4.y;
            Ws[c4 + 2][e] = w4.z; Ws[c4 + 3][e] = w4.w;
        }
        __syncthreads();
        #pragma unroll
        for (int c = 0; c < KC; c++) {
            float4 xa = *(const float4*)&Xs[c][tn * 4];
            float xv[4] = {xa.x, xa.y, xa.z, xa.w};
            float wb[4];
            #pragma unroll
            for (int j = 0; j < 4; j++) wb[j] = Ws[c][te * 4 + j];
            #pragma unroll
            for (int i = 0; i < 4; i++)
                #pragma unroll
                for (int j = 0; j < 4; j++)
                    acc[i][j] = fmaf(xv[i], wb[j], acc[i][j]);
        }
        __syncthreads();
    }
    // Stage [32 e][128 n] into Xs (loop's final sync freed it), tf32-rounded.
    #pragma unroll
    for (int j = 0; j < 4; j++) {
        *(float4*)&Xs[te * 4 + j][tn * 4] = make_float4(
            __uint_as_float(to_tf32_bits(acc[0][j])),
            __uint_as_float(to_tf32_bits(acc[1][j])),
            __uint_as_float(to_tf32_bits(acc[2][j])),
            __uint_as_float(to_tf32_bits(acc[3][j])));
    }
    __syncthreads();
    // Coalesced interleaved store: gather kinv from smem, float4 to gmem.
    const int e_loc  = tid >> 3;
    const int dbase  = (tid & 7) * 4;
    #pragma unroll
    for (int blk = 0; blk < 4; blk++) {
        const float* srow = &Xs[e_loc][blk * 32];
        float4 o;
        o.x = srow[kinv(dbase + 0)];
        o.y = srow[kinv(dbase + 1)];
        o.z = srow[kinv(dbase + 2)];
        o.w = srow[kinv(dbase + 3)];
        *(float4*)&out[((size_t)b * Etot + e0 + e_loc) * HW + n0 + blk * 32 + dbase] = o;
    }
}

// ===========================================================================
// Flash attention: fp32 S on FFMA, tf32 mma.sync P*V, SOFTWARE-PIPELINED:
// per barrier interval, MMA(tile t) and S(tile t+1) run concurrently.
// CTA: 64 m x 256 e. MMA warp tile = 32m x 64e. Double-buffered Ks/Ps/Vs.
// ===========================================================================
constexpr int MT = 64;
constexpr int NT = 32;
constexpr int NTILES = HW / NT;   // 128

constexpr int ST_PV  = 34;   // Ps/Vs row stride (floats)
constexpr int ST_STG = 130;  // epilogue stage stride

constexpr int KS_STRIDE = 32 * 36;       // 1152
constexpr int PS_STRIDE = 64 * ST_PV;    // 2176
constexpr int VS_STRIDE = 256 * ST_PV;   // 8704

constexpr int QS_OFF  = 0;                        // [64][32]        = 2048
constexpr int KS_OFF  = QS_OFF + 64 * 32;         // 2 x [32][36]    = 2304
constexpr int PS_OFF  = KS_OFF + 2 * KS_STRIDE;   // 2 x [64][34]    = 4352
constexpr int INV_OFF = PS_OFF + 2 * PS_STRIDE;   // [64]
constexpr int VS_OFF  = INV_OFF + 64;             // 2 x [256][34]   = 17408 (Stage overlays)
constexpr int FLASH_FLOATS = VS_OFF + 2 * VS_STRIDE;   // 26176
constexpr int FLASH_SMEM = FLASH_FLOATS * 4;           // 104704 B

__global__ __launch_bounds__(256, 2) void flash_kernel(
    const float* __restrict__ x, const float* __restrict__ gamma_p,
    float* __restrict__ out)
{
    extern __shared__ __align__(16) float sm[];
    float* Qs    = sm + QS_OFF;
    float* Ks    = sm + KS_OFF;
    float* Ps    = sm + PS_OFF;
    float* invs  = sm + INV_OFF;
    float* Vs    = sm + VS_OFF;
    float* Stage = sm + VS_OFF;   // reused in epilogue

    const int tid  = threadIdx.x;
    const int wid  = tid >> 5;
    const int lane = tid & 31;
    const int b    = blockIdx.y;
    const int m0   = blockIdx.x * MT;

    // Resident K-block (attention "queries"): Qs[m][d], m in [0,64)
    #pragma unroll
    for (int r = 0; r < 2; r++) {
        int idx = tid + 256 * r;
        int m = idx >> 3, d4 = (idx & 7) * 4;
        *(float4*)&Qs[m * 32 + d4] =
            *(const float4*)&g_k[((size_t)b * HW + m0 + m) * D + d4];
    }

    const int tm = wid;              // S-phase warp row block
    const int g  = lane >> 2;
    const int tg = lane & 3;
    const int pm = (wid & 1) * 32;   // mma m-block
    const int pe = (wid >> 1) * 64;  // mma e-block

    float acc[2][8][4] = {};
    float rsum[8] = {};

    const int ldn  = tid >> 3;
    const int ldd4 = (tid & 7) * 4;
    const int fl   = ((lane & 3) << 3) + ((lane >> 3) << 1) + ((lane >> 2) & 1);

    // Hoisted gmem pointers (advance by constant per tile)
    const float* qptr = g_q + ((size_t)b * HW + ldn) * D + ldd4;
    const float* vptr = g_v + ((size_t)b * C + ldn) * HW + ldd4;

    // S phase for one tile: Kb = Ks buffer, Pb = Ps buffer
    auto s_phase = [&](const float* Kb, float* Pb) {
        float s[8] = {};
        #pragma unroll
        for (int d4 = 0; d4 < 8; d4++) {
            float4 kv = *(const float4*)&Kb[lane * 36 + d4 * 4];
            #pragma unroll
            for (int i = 0; i < 8; i++) {
                float4 qv = *(const float4*)&Qs[(tm * 8 + i) * 32 + d4 * 4];
                s[i] = fmaf(qv.x, kv.x, s[i]);
                s[i] = fmaf(qv.y, kv.y, s[i]);
                s[i] = fmaf(qv.z, kv.z, s[i]);
                s[i] = fmaf(qv.w, kv.w, s[i]);
            }
        }
        #pragma unroll
        for (int i = 0; i < 8; i++) {
            float pt = __uint_as_float(to_tf32_bits(__expf(s[i])));
            rsum[i] += pt;
            Pb[(tm * 8 + i) * ST_PV + fl] = pt;
        }
    };

    // Load gmem tile -> smem buffer bufsel (K and V)
    auto load_tile = [&](int bufsel) {
        float4 kq = *(const float4*)qptr;
        *(float4*)&Ks[bufsel * KS_STRIDE + ldn * 36 + ldd4] = kq;
        float* vb = Vs + bufsel * VS_STRIDE;
        #pragma unroll
        for (int p = 0; p < 8; p++) {
            float4 v4 = *(const float4*)(vptr + (size_t)(32 * p) * HW);
            float2* dst = (float2*)&vb[(ldn + 32 * p) * ST_PV + ldd4];
            dst[0] = make_float2(v4.x, v4.y);
            dst[1] = make_float2(v4.z, v4.w);
        }
        qptr += NT * D;
        vptr += NT;
    };

    // Prologue: tile 0 into buffer 0, then S(0)
    load_tile(0);
    __syncthreads();
    s_phase(Ks, Ps);

    for (int t = 0; t < NTILES; t++) {
        const int buf = t & 1, nxt = buf ^ 1;
        if (t + 1 < NTILES) load_tile(nxt);
        __syncthreads();   // BAR A: K/V(t+1) + Ps(t) ready

        // MMA(t): acc += P(t) * V(t)
        {
            const float* Pb = Ps + buf * PS_STRIDE;
            const float* Vb = Vs + buf * VS_STRIDE;
            #pragma unroll
            for (int kk = 0; kk < 4; kk++) {
                const int fo = 8 * tg + 2 * kk;
                float2 aA[2][2];
                #pragma unroll
                for (int mb = 0; mb < 2; mb++) {
                    aA[mb][0] = *(const float2*)&Pb[(pm + mb * 16 + g) * ST_PV + fo];
                    aA[mb][1] = *(const float2*)&Pb[(pm + mb * 16 + g + 8) * ST_PV + fo];
                }
                #pragma unroll
                for (int nb = 0; nb < 8; nb++) {
                    float2 bb = *(const float2*)&Vb[(pe + nb * 8 + g) * ST_PV + fo];
                    uint32_t b0 = __float_as_uint(bb.x);
                    uint32_t b1 = __float_as_uint(bb.y);
                    #pragma unroll
                    for (int mb = 0; mb < 2; mb++) {
                        mma_tf32_16x8x8(acc[mb][nb][0], acc[mb][nb][1],
                                        acc[mb][nb][2], acc[mb][nb][3],
                                        __float_as_uint(aA[mb][0].x),
                                        __float_as_uint(aA[mb][1].x),
                                        __float_as_uint(aA[mb][0].y),
                                        __float_as_uint(aA[mb][1].y),
                                        b0, b1);
                    }
                }
            }
        }
        // S(t+1): overlaps MMA(t) across warps within this interval
        if (t + 1 < NTILES)
            s_phase(Ks + nxt * KS_STRIDE, Ps + nxt * PS_STRIDE);
        __syncthreads();   // BAR B: protect Vs[buf] from next interval's STS
    }

    // Row-sum reduction -> invs[m] = gamma / rsum[m]
    const float gamma = *gamma_p;
    #pragma unroll
    for (int i = 0; i < 8; i++) {
        float tsum = rsum[i];
        #pragma unroll
        for (int off = 16; off > 0; off >>= 1)
            tsum += __shfl_xor_sync(0xffffffffu, tsum, off);
        if (lane == 0) invs[tm * 8 + i] = gamma / tsum;
    }
    __syncthreads();

    // Epilogue: two e-halves staged [64][130], coalesced residual-add stores.
    const int ml  = (lane & 15) * 4;
    const int sub = lane >> 4;
    #pragma unroll
    for (int half = 0; half < 2; half++) {
        if ((wid >> 2) == half) {
            const int pe_loc = ((wid >> 1) & 1) * 64;
            #pragma unroll
            for (int mb = 0; mb < 2; mb++) {
                const int r0 = pm + mb * 16 + g;
                const int r1 = r0 + 8;
                const float i0 = invs[r0];
                const float i1 = invs[r1];
                #pragma unroll
                for (int nb = 0; nb < 8; nb++) {
                    int col = pe_loc + nb * 8 + tg * 2;
                    *(float2*)&Stage[r0 * ST_STG + col] =
                        make_float2(acc[mb][nb][0] * i0, acc[mb][nb][1] * i0);
                    *(float2*)&Stage[r1 * ST_STG + col] =
                        make_float2(acc[mb][nb][2] * i1, acc[mb][nb][3] * i1);
                }
            }
        }
        __syncthreads();
        #pragma unroll
        for (int it = 0; it < 8; it++) {
            int e_loc = it * 16 + wid * 2 + sub;
            int eg = half * 128 + e_loc;
            size_t idx = ((size_t)b * C + eg) * HW + m0 + ml;
            float4 xv = *(const float4*)&x[idx];
            float4 ov;
            ov.x = Stage[(ml + 0) * ST_STG + e_loc] + xv.x;
            ov.y = Stage[(ml + 1) * ST_STG + e_loc] + xv.y;
            ov.z = Stage[(ml + 2) * ST_STG + e_loc] + xv.z;
            ov.w = Stage[(ml + 3) * ST_STG + e_loc] + xv.w;
            *(float4*)&out[idx] = ov;
        }
        __syncthreads();
    }
}

// ===========================================================================
extern "C" void kernel_launch(void* const* d_in, const int* in_sizes, int n_in,
                              void* d_out, int out_size)
{
    const float* x     = (const float*)d_in[0];
    const float* Wq    = (const float*)d_in[1];
    const float* Wk    = (const float*)d_in[2];
    const float* Wv    = (const float*)d_in[3];
    const float* gamma = (const float*)d_in[4];
    float* out = (float*)d_out;

    void *qp, *kp, *vp;
    cudaGetSymbolAddress(&qp, g_q);
    cudaGetSymbolAddress(&kp, g_k);
    cudaGetSymbolAddress(&vp, g_v);

    static bool attr_set = false;
    if (!attr_set) {
        cudaFuncSetAttribute(flash_kernel,
                             cudaFuncAttributeMaxDynamicSharedMemorySize,
                             FLASH_SMEM);
        attr_set = true;
    }

    dim3 blk(256);
    proj_kernel  <<<dim3(HW / 128, B, 1), blk>>>(x, Wq, (float*)qp, D);
    proj_kernel  <<<dim3(HW / 128, B, 1), blk>>>(x, Wk, (float*)kp, D);
    proj_kernel_T<<<dim3(HW / 128, B, 8), blk>>>(x, Wv, (float*)vp, C);
    flash_kernel<<<dim3(HW / MT, B), blk, FLASH_SMEM>>>(x, gamma, out);
}

// round 11
// speedup vs baseline: 1.0586x; 1.0259x over previous
#include <cuda_runtime.h>
#include <cstdint>
#include <math.h>

constexpr int B  = 16;
constexpr int C  = 256;
constexpr int HW = 4096;
constexpr int D  = 32;

__device__ float g_q[B * HW * D];   // [b][n][kperm(d)]  fp32, d-interleaved
__device__ float g_k[B * HW * D];   // [b][m][d]         fp32 plain
__device__ float g_v[B * HW * C];   // [b][e][tile][kperm(n)]  tf32-rounded

// cvt.rna.tf32.f32: destination is a .b32 register (tf32 bit pattern).
__device__ __forceinline__ uint32_t to_tf32_bits(float x) {
    uint32_t r;
    asm("cvt.rna.tf32.f32 %0, %1;" : "=r"(r) : "f"(x));
    return r;
}

// tf32 mma: A/B fragments are .b32 regs, C/D are .f32
__device__ __forceinline__ void mma_tf32_16x8x8(
    float& c0, float& c1, float& c2, float& c3,
    uint32_t a0, uint32_t a1, uint32_t a2, uint32_t a3,
    uint32_t b0, uint32_t b1)
{
    asm volatile(
        "mma.sync.aligned.m16n8k8.row.col.f32.tf32.tf32.f32 "
        "{%0,%1,%2,%3}, {%4,%5,%6,%7}, {%8,%9}, {%0,%1,%2,%3};"
        : "+f"(c0), "+f"(c1), "+f"(c2), "+f"(c3)
        : "r"(a0), "r"(a1), "r"(a2), "r"(a3), "r"(b0), "r"(b1));
}

// k-interleave within a 32-wide tile (pairs (k, k+4) adjacent) and inverse.
__device__ __forceinline__ int kperm(int k) {
    return ((k & 3) << 3) + ((k >> 3) << 1) + ((k >> 2) & 1);
}
__device__ __forceinline__ int kinv(int d) {
    return (d >> 3) + ((d & 1) << 2) + (((d >> 1) & 3) << 3);
}

// ===========================================================================
// Projection GEMMs: out[b][n][e] = sum_c W[e][c] * x[b][c][n]
// ===========================================================================
__global__ __launch_bounds__(256) void proj_kernel(
    const float* __restrict__ x, const float* __restrict__ W,
    float* __restrict__ out, int Etot)
{
    constexpr int BN = 128, KC = 32;
    __shared__ __align__(16) float Xs[KC][BN + 4];
    __shared__ float Ws[KC][33];
    const int b = blockIdx.y, n0 = blockIdx.x * BN, e0 = blockIdx.z * 32;
    const int tid = threadIdx.x, tn = tid & 31, te = tid >> 5;
    float acc[4][4] = {};
    const float* xb = x + (size_t)b * C * HW;
    for (int c0 = 0; c0 < C; c0 += KC) {
        #pragma unroll
        for (int r = 0; r < 4; r++) {
            int idx = tid + 256 * r;
            int c = idx >> 5, n4 = (idx & 31) * 4;
            *(float4*)&Xs[c][n4] = *(const float4*)&xb[(size_t)(c0 + c) * HW + n0 + n4];
        }
        {
            int e = tid >> 3, c4 = (tid & 7) * 4;
            float4 w4 = *(const float4*)&W[(size_t)(e0 + e) * C + c0 + c4];
            Ws[c4 + 0][e] = w4.x; Ws[c4 + 1][e] = w4.y;
            Ws[c4 + 2][e] = w4.z; Ws[c4 + 3][e] = w4.w;
        }
        __syncthreads();
        #pragma unroll
        for (int c = 0; c < KC; c++) {
            float4 xa = *(const float4*)&Xs[c][tn * 4];
            float xv[4] = {xa.x, xa.y, xa.z, xa.w};
            float wb[4];
            #pragma unroll
            for (int j = 0; j < 4; j++) wb[j] = Ws[c][te * 4 + j];
            #pragma unroll
            for (int i = 0; i < 4; i++)
                #pragma unroll
                for (int j = 0; j < 4; j++)
                    acc[i][j] = fmaf(xv[i], wb[j], acc[i][j]);
        }
        __syncthreads();
    }
    #pragma unroll
    for (int i = 0; i < 4; i++) {
        float4 o4 = make_float4(acc[i][0], acc[i][1], acc[i][2], acc[i][3]);
        int n = n0 + tn * 4 + i;
        *(float4*)&out[((size_t)b * HW + n) * Etot + e0 + te * 4] = o4;
    }
}

// q projection: same GEMM, stores fp32 d-INTERLEAVED: out[b][n][kperm(d)].
__global__ __launch_bounds__(256) void proj_kernel_QI(
    const float* __restrict__ x, const float* __restrict__ W,
    float* __restrict__ out)
{
    constexpr int BN = 128, KC = 32;
    __shared__ __align__(16) float Xs[KC][BN + 4];
    __shared__ float Ws[KC][33];
    const int b = blockIdx.y, n0 = blockIdx.x * BN;
    const int tid = threadIdx.x, tn = tid & 31, te = tid >> 5;
    float acc[4][4] = {};
    const float* xb = x + (size_t)b * C * HW;
    for (int c0 = 0; c0 < C; c0 += KC) {
        #pragma unroll
        for (int r = 0; r < 4; r++) {
            int idx = tid + 256 * r;
            int c = idx >> 5, n4 = (idx & 31) * 4;
            *(float4*)&Xs[c][n4] = *(const float4*)&xb[(size_t)(c0 + c) * HW + n0 + n4];
        }
        {
            int e = tid >> 3, c4 = (tid & 7) * 4;
            float4 w4 = *(const float4*)&W[(size_t)e * C + c0 + c4];
            Ws[c4 + 0][e] = w4.x; Ws[c4 + 1][e] = w4.y;
            Ws[c4 + 2][e] = w4.z; Ws[c4 + 3][e] = w4.w;
        }
        __syncthreads();
        #pragma unroll
        for (int c = 0; c < KC; c++) {
            float4 xa = *(const float4*)&Xs[c][tn * 4];
            float xv[4] = {xa.x, xa.y, xa.z, xa.w};
            float wb[4];
            #pragma unroll
            for (int j = 0; j < 4; j++) wb[j] = Ws[c][te * 4 + j];
            #pragma unroll
            for (int i = 0; i < 4; i++)
                #pragma unroll
                for (int j = 0; j < 4; j++)
                    acc[i][j] = fmaf(xv[i], wb[j], acc[i][j]);
        }
        __syncthreads();
    }
    #pragma unroll
    for (int i = 0; i < 4; i++) {
        int n = n0 + tn * 4 + i;
        float* orow = &out[((size_t)b * HW + n) * 32];
        #pragma unroll
        for (int j = 0; j < 4; j++)
            orow[kperm(te * 4 + j)] = acc[i][j];
    }
}

// V projection: transposed + tf32-rounded + k-interleaved, smem-staged
// COALESCED float4 stores.
__global__ __launch_bounds__(256) void proj_kernel_T(
    const float* __restrict__ x, const float* __restrict__ W,
    float* __restrict__ out, int Etot)
{
    constexpr int BN = 128, KC = 32;
    __shared__ __align__(16) float Xs[KC][BN + 4];
    __shared__ float Ws[KC][33];
    const int b = blockIdx.y, n0 = blockIdx.x * BN, e0 = blockIdx.z * 32;
    const int tid = threadIdx.x, tn = tid & 31, te = tid >> 5;
    float acc[4][4] = {};
    const float* xb = x + (size_t)b * C * HW;
    for (int c0 = 0; c0 < C; c0 += KC) {
        #pragma unroll
        for (int r = 0; r < 4; r++) {
            int idx = tid + 256 * r;
            int c = idx >> 5, n4 = (idx & 31) * 4;
            *(float4*)&Xs[c][n4] = *(const float4*)&xb[(size_t)(c0 + c) * HW + n0 + n4];
        }
        {
            int e = tid >> 3, c4 = (tid & 7) * 4;
            float4 w4 = *(const float4*)&W[(size_t)(e0 + e) * C + c0 + c4];
            Ws[c4 + 0][e] = w4.x; Ws[c4 + 1][e] = w4.y;
            Ws[c4 + 2][e] = w4.z; Ws[c4 + 3][e] = w4.w;
        }
        __syncthreads();
        #pragma unroll
        for (int c = 0; c < KC; c++) {
            float4 xa = *(const float4*)&Xs[c][tn * 4];
            float xv[4] = {xa.x, xa.y, xa.z, xa.w};
            float wb[4];
            #pragma unroll
            for (int j = 0; j < 4; j++) wb[j] = Ws[c][te * 4 + j];
            #pragma unroll
            for (int i = 0; i < 4; i++)
                #pragma unroll
                for (int j = 0; j < 4; j++)
                    acc[i][j] = fmaf(xv[i], wb[j], acc[i][j]);
        }
        __syncthreads();
    }
    #pragma unroll
    for (int j = 0; j < 4; j++) {
        *(float4*)&Xs[te * 4 + j][tn * 4] = make_float4(
            __uint_as_float(to_tf32_bits(acc[0][j])),
            __uint_as_float(to_tf32_bits(acc[1][j])),
            __uint_as_float(to_tf32_bits(acc[2][j])),
            __uint_as_float(to_tf32_bits(acc[3][j])));
    }
    __syncthreads();
    const int e_loc  = tid >> 3;
    const int dbase  = (tid & 7) * 4;
    #pragma unroll
    for (int blk = 0; blk < 4; blk++) {
        const float* srow = &Xs[e_loc][blk * 32];
        float4 o;
        o.x = srow[kinv(dbase + 0)];
        o.y = srow[kinv(dbase + 1)];
        o.z = srow[kinv(dbase + 2)];
        o.w = srow[kinv(dbase + 3)];
        *(float4*)&out[((size_t)b * Etot + e0 + e_loc) * HW + n0 + blk * 32 + dbase] = o;
    }
}

// ===========================================================================
// Flash attention: BOTH GEMMs on tensor cores.
//   S = K*q^T via split-tf32 (Ah*qh + Ah*ql + Al*qh), K frags register-resident.
//   P*V via tf32 as before. exp on register C-frags; rsum via register
//   partials + one final smem atomic combine.
// CTA: 64 m x 256 e. PV warp tile 32m x 64e. S warp tile 16m x 16n.
// ===========================================================================
constexpr int MT = 64;
constexpr int NT = 32;
constexpr int NTILES = HW / NT;   // 128

constexpr int ST_PV  = 34;   // q/Ps/Vs row stride (floats)
constexpr int ST_STG = 130;  // epilogue stage stride

constexpr int Q_STRIDE  = 32 * ST_PV;    // 1088
constexpr int PS_STRIDE = 64 * ST_PV;    // 2176
constexpr int VS_STRIDE = 256 * ST_PV;   // 8704

constexpr int QS_OFF  = 0;                        // 2 x [32][34]
constexpr int PS_OFF  = QS_OFF + 2 * Q_STRIDE;    // 2 x [64][34]
constexpr int INV_OFF = PS_OFF + 2 * PS_STRIDE;   // [64]
constexpr int VS_OFF  = INV_OFF + 64;             // 2 x [256][34] (Stage overlays)
constexpr int FLASH_FLOATS = VS_OFF + 2 * VS_STRIDE;   // 24000
constexpr int FLASH_SMEM = FLASH_FLOATS * 4;           // 96000 B

__global__ __launch_bounds__(256, 2) void flash_kernel(
    const float* __restrict__ x, const float* __restrict__ gamma_p,
    float* __restrict__ out)
{
    extern __shared__ __align__(16) float sm[];
    float* Qsm   = sm + QS_OFF;
    float* Ps    = sm + PS_OFF;
    float* invs  = sm + INV_OFF;
    float* Vs    = sm + VS_OFF;
    float* Stage = sm + VS_OFF;   // reused in epilogue

    const int tid  = threadIdx.x;
    const int wid  = tid >> 5;
    const int lane = tid & 31;
    const int b    = blockIdx.y;
    const int m0   = blockIdx.x * MT;

    const int g  = lane >> 2;        // mma row-in-halftile
    const int tg = lane & 3;         // mma thread-in-group (k)
    const int pm = (wid & 1) * 32;   // PV m-block
    const int pe = (wid >> 1) * 64;  // PV e-block
    const int mbW = wid & 3;         // S m16-block
    const int nb0 = (wid >> 2) * 2;  // S n8-blocks nb0, nb0+1

    if (tid < 64) invs[tid] = 0.0f;

    // Kernel-lifetime K A-fragments (hi/lo split) for S m-block mbW.
    uint32_t Ah[4][4], Al[4][4];
    {
        const float* kb = g_k + ((size_t)b * HW + m0 + mbW * 16) * D;
        #pragma unroll
        for (int kk = 0; kk < 4; kk++) {
            float f[4];
            f[0] = kb[g * D + kk * 8 + tg];
            f[1] = kb[(g + 8) * D + kk * 8 + tg];
            f[2] = kb[g * D + kk * 8 + tg + 4];
            f[3] = kb[(g + 8) * D + kk * 8 + tg + 4];
            #pragma unroll
            for (int i = 0; i < 4; i++) {
                uint32_t h = to_tf32_bits(f[i]);
                Ah[kk][i] = h;
                Al[kk][i] = to_tf32_bits(f[i] - __uint_as_float(h));
            }
        }
    }

    float acc[2][8][4] = {};
    float rs0 = 0.0f, rs1 = 0.0f;   // rsum partials: rows mbW*16+g, +8

    const int ldn  = tid >> 3;
    const int ldd4 = (tid & 7) * 4;

    const float* qptr = g_q + ((size_t)b * HW + ldn) * D + ldd4;
    const float* vptr = g_v + ((size_t)b * C + ldn) * HW + ldd4;

    // Load gmem tile (q + V) into smem buffer bufsel
    auto load_tile = [&](int bufsel) {
        float4 q4 = *(const float4*)qptr;
        float2* qd = (float2*)&Qsm[bufsel * Q_STRIDE + ldn * ST_PV + ldd4];
        qd[0] = make_float2(q4.x, q4.y);
        qd[1] = make_float2(q4.z, q4.w);
        float* vb = Vs + bufsel * VS_STRIDE;
        #pragma unroll
        for (int p = 0; p < 8; p++) {
            float4 v4 = *(const float4*)(vptr + (size_t)(32 * p) * HW);
            float2* dst = (float2*)&vb[(ldn + 32 * p) * ST_PV + ldd4];
            dst[0] = make_float2(v4.x, v4.y);
            dst[1] = make_float2(v4.z, v4.w);
        }
        qptr += NT * D;
        vptr += NT;
    };

    // S phase on tensor cores: 2 m16n8 tiles (mbW, nb0/nb0+1), split-tf32.
    auto s_phase = [&](int bufsel) {
        const float* Qb = Qsm + bufsel * Q_STRIDE;
        float* Pb = Ps + bufsel * PS_STRIDE;
        #pragma unroll
        for (int nt = 0; nt < 2; nt++) {
            const int nb = nb0 + nt;
            float sC[4] = {0.f, 0.f, 0.f, 0.f};
            const float* pQ = Qb + (nb * 8 + g) * ST_PV + 8 * tg;
            #pragma unroll
            for (int kk = 0; kk < 4; kk++) {
                float2 qf = *(const float2*)&pQ[2 * kk];
                uint32_t bh0 = to_tf32_bits(qf.x);
                uint32_t bh1 = to_tf32_bits(qf.y);
                uint32_t bl0 = to_tf32_bits(qf.x - __uint_as_float(bh0));
                uint32_t bl1 = to_tf32_bits(qf.y - __uint_as_float(bh1));
                mma_tf32_16x8x8(sC[0], sC[1], sC[2], sC[3],
                                Ah[kk][0], Ah[kk][1], Ah[kk][2], Ah[kk][3],
                                bh0, bh1);
                mma_tf32_16x8x8(sC[0], sC[1], sC[2], sC[3],
                                Ah[kk][0], Ah[kk][1], Ah[kk][2], Ah[kk][3],
                                bl0, bl1);
                mma_tf32_16x8x8(sC[0], sC[1], sC[2], sC[3],
                                Al[kk][0], Al[kk][1], Al[kk][2], Al[kk][3],
                                bh0, bh1);
            }
            // exp + tf32-round; store P at kperm'd k-positions; rsum partials.
            const int fl = 16 * (tg & 1) + 2 * nb + (tg >> 1);
            float p0 = __uint_as_float(to_tf32_bits(__expf(sC[0])));
            float p1 = __uint_as_float(to_tf32_bits(__expf(sC[1])));
            float p2 = __uint_as_float(to_tf32_bits(__expf(sC[2])));
            float p3 = __uint_as_float(to_tf32_bits(__expf(sC[3])));
            const int r0 = mbW * 16 + g;
            Pb[r0 * ST_PV + fl]           = p0;
            Pb[r0 * ST_PV + fl + 8]       = p1;
            Pb[(r0 + 8) * ST_PV + fl]     = p2;
            Pb[(r0 + 8) * ST_PV + fl + 8] = p3;
            rs0 += p0 + p1;
            rs1 += p2 + p3;
        }
    };

    // Prologue
    load_tile(0);
    __syncthreads();
    s_phase(0);

    for (int t = 0; t < NTILES; t++) {
        const int buf = t & 1, nxt = buf ^ 1;
        if (t + 1 < NTILES) load_tile(nxt);
        __syncthreads();   // BAR A: q/V(t+1) staged, Ps(t) complete

        // PV(t): acc[32m x 64e] += P(t) * V(t)   (immediate-offset addressing)
        {
            const float* pA = Ps + buf * PS_STRIDE + (pm + g) * ST_PV + 8 * tg;
            const float* pB = Vs + buf * VS_STRIDE + (pe + g) * ST_PV + 8 * tg;
            #pragma unroll
            for (int kk = 0; kk < 4; kk++) {
                float2 a00 = *(const float2*)&pA[2 * kk];                 // rows pm+g
                float2 a01 = *(const float2*)&pA[8 * ST_PV + 2 * kk];     // pm+g+8
                float2 a10 = *(const float2*)&pA[16 * ST_PV + 2 * kk];    // pm+16+g
                float2 a11 = *(const float2*)&pA[24 * ST_PV + 2 * kk];    // pm+24+g
                #pragma unroll
                for (int nb = 0; nb < 8; nb++) {
                    float2 bb = *(const float2*)&pB[nb * 8 * ST_PV + 2 * kk];
                    uint32_t b0 = __float_as_uint(bb.x);
                    uint32_t b1 = __float_as_uint(bb.y);
                    mma_tf32_16x8x8(acc[0][nb][0], acc[0][nb][1],
                                    acc[0][nb][2], acc[0][nb][3],
                                    __float_as_uint(a00.x), __float_as_uint(a01.x),
                                    __float_as_uint(a00.y), __float_as_uint(a01.y),
                                    b0, b1);
                    mma_tf32_16x8x8(acc[1][nb][0], acc[1][nb][1],
                                    acc[1][nb][2], acc[1][nb][3],
                                    __float_as_uint(a10.x), __float_as_uint(a11.x),
                                    __float_as_uint(a10.y), __float_as_uint(a11.y),
                                    b0, b1);
                }
            }
        }
        // S(t+1) overlaps PV(t)
        if (t + 1 < NTILES) s_phase(nxt);
        __syncthreads();   // BAR B: protect q/V/Ps(buf) from next load/S
    }

    // Combine rsum partials: reduce over tg (quad lanes), then atomics to invs.
    rs0 += __shfl_xor_sync(0xffffffffu, rs0, 1);
    rs0 += __shfl_xor_sync(0xffffffffu, rs0, 2);
    rs1 += __shfl_xor_sync(0xffffffffu, rs1, 1);
    rs1 += __shfl_xor_sync(0xffffffffu, rs1, 2);
    if (tg == 0) {
        atomicAdd(&invs[mbW * 16 + g], rs0);
        atomicAdd(&invs[mbW * 16 + 8 + g], rs1);
    }
    __syncthreads();
    const float gamma = *gamma_p;
    if (tid < 64) invs[tid] = gamma / invs[tid];
    __syncthreads();

    // Epilogue: two e-halves staged [64][130], coalesced residual-add stores.
    const int ml  = (lane & 15) * 4;
    const int sub = lane >> 4;
    #pragma unroll
    for (int half = 0; half < 2; half++) {
        if ((wid >> 2) == half) {
            const int pe_loc = ((wid >> 1) & 1) * 64;
            #pragma unroll
            for (int mb = 0; mb < 2; mb++) {
                const int r0 = pm + mb * 16 + g;
                const int r1 = r0 + 8;
                const float i0 = invs[r0];
                const float i1 = invs[r1];
                #pragma unroll
                for (int nb = 0; nb < 8; nb++) {
                    int col = pe_loc + nb * 8 + tg * 2;
                    *(float2*)&Stage[r0 * ST_STG + col] =
                        make_float2(acc[mb][nb][0] * i0, acc[mb][nb][1] * i0);
                    *(float2*)&Stage[r1 * ST_STG + col] =
                        make_float2(acc[mb][nb][2] * i1, acc[mb][nb][3] * i1);
                }
            }
        }
        __syncthreads();
        #pragma unroll
        for (int it = 0; it < 8; it++) {
            int e_loc = it * 16 + wid * 2 + sub;
            int eg = half * 128 + e_loc;
            size_t idx = ((size_t)b * C + eg) * HW + m0 + ml;
            float4 xv = *(const float4*)&x[idx];
            float4 ov;
            ov.x = Stage[(ml + 0) * ST_STG + e_loc] + xv.x;
            ov.y = Stage[(ml + 1) * ST_STG + e_loc] + xv.y;
            ov.z = Stage[(ml + 2) * ST_STG + e_loc] + xv.z;
            ov.w = Stage[(ml + 3) * ST_STG + e_loc] + xv.w;
            *(float4*)&out[idx] = ov;
        }
        __syncthreads();
    }
}

// ===========================================================================
extern "C" void kernel_launch(void* const* d_in, const int* in_sizes, int n_in,
                              void* d_out, int out_size)
{
    const float* x     = (const float*)d_in[0];
    const float* Wq    = (const float*)d_in[1];
    const float* Wk    = (const float*)d_in[2];
    const float* Wv    = (const float*)d_in[3];
    const float* gamma = (const float*)d_in[4];
    float* out = (float*)d_out;

    void *qp, *kp, *vp;
    cudaGetSymbolAddress(&qp, g_q);
    cudaGetSymbolAddress(&kp, g_k);
    cudaGetSymbolAddress(&vp, g_v);

    static bool attr_set = false;
    if (!attr_set) {
        cudaFuncSetAttribute(flash_kernel,
                             cudaFuncAttributeMaxDynamicSharedMemorySize,
                             FLASH_SMEM);
        attr_set = true;
    }

    dim3 blk(256);
    proj_kernel_QI<<<dim3(HW / 128, B, 1), blk>>>(x, Wq, (float*)qp);
    proj_kernel   <<<dim3(HW / 128, B, 1), blk>>>(x, Wk, (float*)kp, D);
    proj_kernel_T <<<dim3(HW / 128, B, 8), blk>>>(x, Wv, (float*)vp, C);
    flash_kernel<<<dim3(HW / MT, B), blk, FLASH_SMEM>>>(x, gamma, out);
}

// round 12
// speedup vs baseline: 1.0651x; 1.0062x over previous
#include <cuda_runtime.h>
#include <cstdint>
#include <math.h>

constexpr int B  = 16;
constexpr int C  = 256;
constexpr int HW = 4096;
constexpr int D  = 32;

constexpr int MT = 64;
constexpr int NT = 32;
constexpr int NTILES = HW / NT;   // 128

__device__ float g_q[B * HW * D];   // [b][n][kperm(d)]       fp32
__device__ float g_k[B * HW * D];   // [b][m][d]              fp32 plain
__device__ float g_v[B * HW * C];   // [b][tile][e][kperm(k)] tf32-rounded, tile-major

// cvt.rna.tf32.f32: destination is a .b32 register (tf32 bit pattern).
__device__ __forceinline__ uint32_t to_tf32_bits(float x) {
    uint32_t r;
    asm("cvt.rna.tf32.f32 %0, %1;" : "=r"(r) : "f"(x));
    return r;
}

// tf32 mma: A/B fragments are .b32 regs, C/D are .f32
__device__ __forceinline__ void mma_tf32_16x8x8(
    float& c0, float& c1, float& c2, float& c3,
    uint32_t a0, uint32_t a1, uint32_t a2, uint32_t a3,
    uint32_t b0, uint32_t b1)
{
    asm volatile(
        "mma.sync.aligned.m16n8k8.row.col.f32.tf32.tf32.f32 "
        "{%0,%1,%2,%3}, {%4,%5,%6,%7}, {%8,%9}, {%0,%1,%2,%3};"
        : "+f"(c0), "+f"(c1), "+f"(c2), "+f"(c3)
        : "r"(a0), "r"(a1), "r"(a2), "r"(a3), "r"(b0), "r"(b1));
}

// k-interleave within a 32-wide tile (pairs (k, k+4) adjacent) and inverse.
__device__ __forceinline__ int kperm(int k) {
    return ((k & 3) << 3) + ((k >> 3) << 1) + ((k >> 2) & 1);
}
__device__ __forceinline__ int kinv(int d) {
    return (d >> 3) + ((d & 1) << 2) + (((d >> 1) & 3) << 3);
}

// ===========================================================================
// Projection GEMMs: out[b][n][e] = sum_c W[e][c] * x[b][c][n]
// ===========================================================================
__global__ __launch_bounds__(256) void proj_kernel(
    const float* __restrict__ x, const float* __restrict__ W,
    float* __restrict__ out, int Etot)
{
    constexpr int BN = 128, KC = 32;
    __shared__ __align__(16) float Xs[KC][BN + 4];
    __shared__ float Ws[KC][33];
    const int b = blockIdx.y, n0 = blockIdx.x * BN, e0 = blockIdx.z * 32;
    const int tid = threadIdx.x, tn = tid & 31, te = tid >> 5;
    float acc[4][4] = {};
    const float* xb = x + (size_t)b * C * HW;
    for (int c0 = 0; c0 < C; c0 += KC) {
        #pragma unroll
        for (int r = 0; r < 4; r++) {
            int idx = tid + 256 * r;
            int c = idx >> 5, n4 = (idx & 31) * 4;
            *(float4*)&Xs[c][n4] = *(const float4*)&xb[(size_t)(c0 + c) * HW + n0 + n4];
        }
        {
            int e = tid >> 3, c4 = (tid & 7) * 4;
            float4 w4 = *(const float4*)&W[(size_t)(e0 + e) * C + c0 + c4];
            Ws[c4 + 0][e] = w4.x; Ws[c4 + 1][e] = w4.y;
            Ws[c4 + 2][e] = w4.z; Ws[c4 + 3][e] = w4.w;
        }
        __syncthreads();
        #pragma unroll
        for (int c = 0; c < KC; c++) {
            float4 xa = *(const float4*)&Xs[c][tn * 4];
            float xv[4] = {xa.x, xa.y, xa.z, xa.w};
            float wb[4];
            #pragma unroll
            for (int j = 0; j < 4; j++) wb[j] = Ws[c][te * 4 + j];
            #pragma unroll
            for (int i = 0; i < 4; i++)
                #pragma unroll
                for (int j = 0; j < 4; j++)
                    acc[i][j] = fmaf(xv[i], wb[j], acc[i][j]);
        }
        __syncthreads();
    }
    #pragma unroll
    for (int i = 0; i < 4; i++) {
        float4 o4 = make_float4(acc[i][0], acc[i][1], acc[i][2], acc[i][3]);
        int n = n0 + tn * 4 + i;
        *(float4*)&out[((size_t)b * HW + n) * Etot + e0 + te * 4] = o4;
    }
}

// q projection: stores fp32 d-INTERLEAVED: out[b][n][kperm(d)].
__global__ __launch_bounds__(256) void proj_kernel_QI(
    const float* __restrict__ x, const float* __restrict__ W,
    float* __restrict__ out)
{
    constexpr int BN = 128, KC = 32;
    __shared__ __align__(16) float Xs[KC][BN + 4];
    __shared__ float Ws[KC][33];
    const int b = blockIdx.y, n0 = blockIdx.x * BN;
    const int tid = threadIdx.x, tn = tid & 31, te = tid >> 5;
    float acc[4][4] = {};
    const float* xb = x + (size_t)b * C * HW;
    for (int c0 = 0; c0 < C; c0 += KC) {
        #pragma unroll
        for (int r = 0; r < 4; r++) {
            int idx = tid + 256 * r;
            int c = idx >> 5, n4 = (idx & 31) * 4;
            *(float4*)&Xs[c][n4] = *(const float4*)&xb[(size_t)(c0 + c) * HW + n0 + n4];
        }
        {
            int e = tid >> 3, c4 = (tid & 7) * 4;
            float4 w4 = *(const float4*)&W[(size_t)e * C + c0 + c4];
            Ws[c4 + 0][e] = w4.x; Ws[c4 + 1][e] = w4.y;
            Ws[c4 + 2][e] = w4.z; Ws[c4 + 3][e] = w4.w;
        }
        __syncthreads();
        #pragma unroll
        for (int c = 0; c < KC; c++) {
            float4 xa = *(const float4*)&Xs[c][tn * 4];
            float xv[4] = {xa.x, xa.y, xa.z, xa.w};
            float wb[4];
            #pragma unroll
            for (int j = 0; j < 4; j++) wb[j] = Ws[c][te * 4 + j];
            #pragma unroll
            for (int i = 0; i < 4; i++)
                #pragma unroll
                for (int j = 0; j < 4; j++)
                    acc[i][j] = fmaf(xv[i], wb[j], acc[i][j]);
        }
        __syncthreads();
    }
    #pragma unroll
    for (int i = 0; i < 4; i++) {
        int n = n0 + tn * 4 + i;
        float* orow = &out[((size_t)b * HW + n) * 32];
        #pragma unroll
        for (int j = 0; j < 4; j++)
            orow[kperm(te * 4 + j)] = acc[i][j];
    }
}

// V projection: tf32-rounded, TILE-MAJOR interleaved layout:
//   out[((b*NTILES + t)*C + e)*32 + kperm(k)],  n = t*32 + k.
// Coalesced float4 stores via smem staging.
__global__ __launch_bounds__(256) void proj_kernel_T(
    const float* __restrict__ x, const float* __restrict__ W,
    float* __restrict__ out, int Etot)
{
    constexpr int BN = 128, KC = 32;
    __shared__ __align__(16) float Xs[KC][BN + 4];
    __shared__ float Ws[KC][33];
    const int b = blockIdx.y, n0 = blockIdx.x * BN, e0 = blockIdx.z * 32;
    const int tid = threadIdx.x, tn = tid & 31, te = tid >> 5;
    float acc[4][4] = {};
    const float* xb = x + (size_t)b * C * HW;
    for (int c0 = 0; c0 < C; c0 += KC) {
        #pragma unroll
        for (int r = 0; r < 4; r++) {
            int idx = tid + 256 * r;
            int c = idx >> 5, n4 = (idx & 31) * 4;
            *(float4*)&Xs[c][n4] = *(const float4*)&xb[(size_t)(c0 + c) * HW + n0 + n4];
        }
        {
            int e = tid >> 3, c4 = (tid & 7) * 4;
            float4 w4 = *(const float4*)&W[(size_t)(e0 + e) * C + c0 + c4];
            Ws[c4 + 0][e] = w4.x; Ws[c4 + 1][e] = w4.y;
            Ws[c4 + 2][e] = w4.z; Ws[c4 + 3][e] = w4.w;
        }
        __syncthreads();
        #pragma unroll
        for (int c = 0; c < KC; c++) {
            float4 xa = *(const float4*)&Xs[c][tn * 4];
            float xv[4] = {xa.x, xa.y, xa.z, xa.w};
            float wb[4];
            #pragma unroll
            for (int j = 0; j < 4; j++) wb[j] = Ws[c][te * 4 + j];
            #pragma unroll
            for (int i = 0; i < 4; i++)
                #pragma unroll
                for (int j = 0; j < 4; j++)
                    acc[i][j] = fmaf(xv[i], wb[j], acc[i][j]);
        }
        __syncthreads();
    }
    // Stage [32 e][128 n] tf32-rounded.
    #pragma unroll
    for (int j = 0; j < 4; j++) {
        *(float4*)&Xs[te * 4 + j][tn * 4] = make_float4(
            __uint_as_float(to_tf32_bits(acc[0][j])),
            __uint_as_float(to_tf32_bits(acc[1][j])),
            __uint_as_float(to_tf32_bits(acc[2][j])),
            __uint_as_float(to_tf32_bits(acc[3][j])));
    }
    __syncthreads();
    const int e_loc = tid >> 3;
    const int dbase = (tid & 7) * 4;
    const int t0 = n0 / 32;
    #pragma unroll
    for (int blk = 0; blk < 4; blk++) {
        const float* srow = &Xs[e_loc][blk * 32];
        float4 o;
        o.x = srow[kinv(dbase + 0)];
        o.y = srow[kinv(dbase + 1)];
        o.z = srow[kinv(dbase + 2)];
        o.w = srow[kinv(dbase + 3)];
        *(float4*)&out[(((size_t)b * NTILES + t0 + blk) * C + e0 + e_loc) * 32 + dbase] = o;
    }
}

// ===========================================================================
// Flash attention: both GEMMs on tensor cores.
//   S = K*q^T split-tf32, 2 terms (Ah*qh + Ah*ql); K hi frags register-resident.
//   P*V tf32. Prefetch pipeline: ldg(t+2) before s_phase(t+1); sts(t+1) at
//   loop top (latency hidden behind s_phase + BAR A).
// ===========================================================================
constexpr int ST_PV  = 34;   // q/Ps/Vs row stride (floats)
constexpr int ST_STG = 130;  // epilogue stage stride

constexpr int Q_STRIDE  = 32 * ST_PV;    // 1088
constexpr int PS_STRIDE = 64 * ST_PV;    // 2176
constexpr int VS_STRIDE = 256 * ST_PV;   // 8704

constexpr int QS_OFF  = 0;                        // 2 x [32][34]
constexpr int PS_OFF  = QS_OFF + 2 * Q_STRIDE;    // 2 x [64][34]
constexpr int INV_OFF = PS_OFF + 2 * PS_STRIDE;   // [64]
constexpr int VS_OFF  = INV_OFF + 64;             // 2 x [256][34] (Stage overlays)
constexpr int FLASH_FLOATS = VS_OFF + 2 * VS_STRIDE;
constexpr int FLASH_SMEM = FLASH_FLOATS * 4;      // 96000 B

__global__ __launch_bounds__(256, 2) void flash_kernel(
    const float* __restrict__ x, const float* __restrict__ gamma_p,
    float* __restrict__ out)
{
    extern __shared__ __align__(16) float sm[];
    float* Qsm   = sm + QS_OFF;
    float* Ps    = sm + PS_OFF;
    float* invs  = sm + INV_OFF;
    float* Vs    = sm + VS_OFF;
    float* Stage = sm + VS_OFF;   // reused in epilogue

    const int tid  = threadIdx.x;
    const int wid  = tid >> 5;
    const int lane = tid & 31;
    const int b    = blockIdx.y;
    const int m0   = blockIdx.x * MT;

    const int g  = lane >> 2;
    const int tg = lane & 3;
    const int pm = (wid & 1) * 32;   // PV m-block
    const int pe = (wid >> 1) * 64;  // PV e-block
    const int mbW = wid & 3;         // S m16-block
    const int nb0 = (wid >> 2) * 2;  // S n8-blocks

    if (tid < 64) invs[tid] = 0.0f;

    // Kernel-lifetime K hi-fragments for S m-block mbW (2-term split).
    uint32_t Ah[4][4];
    uint32_t Al_unused; (void)Al_unused;
    {
        const float* kb = g_k + ((size_t)b * HW + m0 + mbW * 16) * D;
        #pragma unroll
        for (int kk = 0; kk < 4; kk++) {
            Ah[kk][0] = to_tf32_bits(kb[g * D + kk * 8 + tg]);
            Ah[kk][1] = to_tf32_bits(kb[(g + 8) * D + kk * 8 + tg]);
            Ah[kk][2] = to_tf32_bits(kb[g * D + kk * 8 + tg + 4]);
            Ah[kk][3] = to_tf32_bits(kb[(g + 8) * D + kk * 8 + tg + 4]);
        }
    }

    float acc[2][8][4] = {};
    float rs0 = 0.0f, rs1 = 0.0f;

    const int ldn  = tid >> 3;
    const int ldd4 = (tid & 7) * 4;

    const float* qptr = g_q + ((size_t)b * HW + ldn) * D + ldd4;
    const float* vptr = g_v + ((size_t)b * NTILES * C + ldn) * 32 + ldd4;  // tile-major

    float4 rq;        // prefetched q
    float4 rv[8];     // prefetched V

    auto ldg_tile = [&]() {
        rq = *(const float4*)qptr;
        #pragma unroll
        for (int p = 0; p < 8; p++)
            rv[p] = *(const float4*)(vptr + p * 32 * 32);   // 4KB immediate steps
        qptr += NT * D;       // 1024 floats
        vptr += C * 32;       // 8192 floats (next tile)
    };
    auto sts_tile = [&](int bufsel) {
        float2* qd = (float2*)&Qsm[bufsel * Q_STRIDE + ldn * ST_PV + ldd4];
        qd[0] = make_float2(rq.x, rq.y);
        qd[1] = make_float2(rq.z, rq.w);
        float* vb = Vs + bufsel * VS_STRIDE;
        #pragma unroll
        for (int p = 0; p < 8; p++) {
            float2* dst = (float2*)&vb[(ldn + 32 * p) * ST_PV + ldd4];
            dst[0] = make_float2(rv[p].x, rv[p].y);
            dst[1] = make_float2(rv[p].z, rv[p].w);
        }
    };

    // S phase on tensor cores, 2-term split-tf32.
    auto s_phase = [&](int bufsel) {
        const float* Qb = Qsm + bufsel * Q_STRIDE;
        float* Pb = Ps + bufsel * PS_STRIDE;
        #pragma unroll
        for (int nt = 0; nt < 2; nt++) {
            const int nb = nb0 + nt;
            float sC[4] = {0.f, 0.f, 0.f, 0.f};
            const float* pQ = Qb + (nb * 8 + g) * ST_PV + 8 * tg;
            #pragma unroll
            for (int kk = 0; kk < 4; kk++) {
                float2 qf = *(const float2*)&pQ[2 * kk];
                uint32_t bh0 = to_tf32_bits(qf.x);
                uint32_t bh1 = to_tf32_bits(qf.y);
                uint32_t bl0 = to_tf32_bits(qf.x - __uint_as_float(bh0));
                uint32_t bl1 = to_tf32_bits(qf.y - __uint_as_float(bh1));
                mma_tf32_16x8x8(sC[0], sC[1], sC[2], sC[3],
                                Ah[kk][0], Ah[kk][1], Ah[kk][2], Ah[kk][3],
                                bh0, bh1);
                mma_tf32_16x8x8(sC[0], sC[1], sC[2], sC[3],
                                Ah[kk][0], Ah[kk][1], Ah[kk][2], Ah[kk][3],
                                bl0, bl1);
            }
            const int fl = 16 * (tg & 1) + 2 * nb + (tg >> 1);
            float p0 = __uint_as_float(to_tf32_bits(__expf(sC[0])));
            float p1 = __uint_as_float(to_tf32_bits(__expf(sC[1])));
            float p2 = __uint_as_float(to_tf32_bits(__expf(sC[2])));
            float p3 = __uint_as_float(to_tf32_bits(__expf(sC[3])));
            const int r0 = mbW * 16 + g;
            Pb[r0 * ST_PV + fl]           = p0;
            Pb[r0 * ST_PV + fl + 8]       = p1;
            Pb[(r0 + 8) * ST_PV + fl]     = p2;
            Pb[(r0 + 8) * ST_PV + fl + 8] = p3;
            rs0 += p0 + p1;
            rs1 += p2 + p3;
        }
    };

    // Prologue: tile 0 staged + scored; tile 1 prefetched to regs.
    ldg_tile();
    sts_tile(0);
    __syncthreads();
    s_phase(0);
    ldg_tile();

    for (int t = 0; t < NTILES; t++) {
        const int buf = t & 1, nxt = buf ^ 1;
        if (t + 1 < NTILES) sts_tile(nxt);      // store prefetched tile t+1
        __syncthreads();   // BAR A: Ps(t) + staged(t+1) ready

        // PV(t): acc[32m x 64e] += P(t) * V(t)
        {
            const float* pA = Ps + buf * PS_STRIDE + (pm + g) * ST_PV + 8 * tg;
            const float* pB = Vs + buf * VS_STRIDE + (pe + g) * ST_PV + 8 * tg;
            #pragma unroll
            for (int kk = 0; kk < 4; kk++) {
                float2 a00 = *(const float2*)&pA[2 * kk];
                float2 a01 = *(const float2*)&pA[8 * ST_PV + 2 * kk];
                float2 a10 = *(const float2*)&pA[16 * ST_PV + 2 * kk];
                float2 a11 = *(const float2*)&pA[24 * ST_PV + 2 * kk];
                #pragma unroll
                for (int nb = 0; nb < 8; nb++) {
                    float2 bb = *(const float2*)&pB[nb * 8 * ST_PV + 2 * kk];
                    uint32_t b0 = __float_as_uint(bb.x);
                    uint32_t b1 = __float_as_uint(bb.y);
                    mma_tf32_16x8x8(acc[0][nb][0], acc[0][nb][1],
                                    acc[0][nb][2], acc[0][nb][3],
                                    __float_as_uint(a00.x), __float_as_uint(a01.x),
                                    __float_as_uint(a00.y), __float_as_uint(a01.y),
                                    b0, b1);
                    mma_tf32_16x8x8(acc[1][nb][0], acc[1][nb][1],
                                    acc[1][nb][2], acc[1][nb][3],
                                    __float_as_uint(a10.x), __float_as_uint(a11.x),
                                    __float_as_uint(a10.y), __float_as_uint(a11.y),
                                    b0, b1);
                }
            }
        }
        __syncthreads();   // BAR B: tile t consumed; staged(t+1) visible

        if (t + 1 < NTILES) {
            if (t + 2 < NTILES) ldg_tile();     // prefetch t+2 (hides L2 latency)
            s_phase(nxt);                       // S(t+1) -> Ps(nxt)
        }
    }

    // Combine rsum partials (quad-lane shfl + smem atomics).
    rs0 += __shfl_xor_sync(0xffffffffu, rs0, 1);
    rs0 += __shfl_xor_sync(0xffffffffu, rs0, 2);
    rs1 += __shfl_xor_sync(0xffffffffu, rs1, 1);
    rs1 += __shfl_xor_sync(0xffffffffu, rs1, 2);
    if (tg == 0) {
        atomicAdd(&invs[mbW * 16 + g], rs0);
        atomicAdd(&invs[mbW * 16 + 8 + g], rs1);
    }
    __syncthreads();
    const float gamma = *gamma_p;
    if (tid < 64) invs[tid] = gamma / invs[tid];
    __syncthreads();

    // Epilogue: two e-halves staged [64][130], coalesced residual-add stores.
    const int ml  = (lane & 15) * 4;
    const int sub = lane >> 4;
    #pragma unroll
    for (int half = 0; half < 2; half++) {
        if ((wid >> 2) == half) {
            const int pe_loc = ((wid >> 1) & 1) * 64;
            #pragma unroll
            for (int mb = 0; mb < 2; mb++) {
                const int r0 = pm + mb * 16 + g;
                const int r1 = r0 + 8;
                const float i0 = invs[r0];
                const float i1 = invs[r1];
                #pragma unroll
                for (int nb = 0; nb < 8; nb++) {
                    int col = pe_loc + nb * 8 + tg * 2;
                    *(float2*)&Stage[r0 * ST_STG + col] =
                        make_float2(acc[mb][nb][0] * i0, acc[mb][nb][1] * i0);
                    *(float2*)&Stage[r1 * ST_STG + col] =
                        make_float2(acc[mb][nb][2] * i1, acc[mb][nb][3] * i1);
                }
            }
        }
        __syncthreads();
        #pragma unroll
        for (int it = 0; it < 8; it++) {
            int e_loc = it * 16 + wid * 2 + sub;
            int eg = half * 128 + e_loc;
            size_t idx = ((size_t)b * C + eg) * HW + m0 + ml;
            float4 xv = *(const float4*)&x[idx];
            float4 ov;
            ov.x = Stage[(ml + 0) * ST_STG + e_loc] + xv.x;
            ov.y = Stage[(ml + 1) * ST_STG + e_loc] + xv.y;
            ov.z = Stage[(ml + 2) * ST_STG + e_loc] + xv.z;
            ov.w = Stage[(ml + 3) * ST_STG + e_loc] + xv.w;
            *(float4*)&out[idx] = ov;
        }
        __syncthreads();
    }
}

// ===========================================================================
extern "C" void kernel_launch(void* const* d_in, const int* in_sizes, int n_in,
                              void* d_out, int out_size)
{
    const float* x     = (const float*)d_in[0];
    const float* Wq    = (const float*)d_in[1];
    const float* Wk    = (const float*)d_in[2];
    const float* Wv    = (const float*)d_in[3];
    const float* gamma = (const float*)d_in[4];
    float* out = (float*)d_out;

    void *qp, *kp, *vp;
    cudaGetSymbolAddress(&qp, g_q);
    cudaGetSymbolAddress(&kp, g_k);
    cudaGetSymbolAddress(&vp, g_v);

    static bool attr_set = false;
    if (!attr_set) {
        cudaFuncSetAttribute(flash_kernel,
                             cudaFuncAttributeMaxDynamicSharedMemorySize,
                             FLASH_SMEM);
        attr_set = true;
    }

    dim3 blk(256);
    proj_kernel_QI<<<dim3(HW / 128, B, 1), blk>>>(x, Wq, (float*)qp);
    proj_kernel   <<<dim3(HW / 128, B, 1), blk>>>(x, Wk, (float*)kp, D);
    proj_kernel_T <<<dim3(HW / 128, B, 8), blk>>>(x, Wv, (float*)vp, C);
    flash_kernel<<<dim3(HW / MT, B), blk, FLASH_SMEM>>>(x, gamma, out);
}

// round 13
// speedup vs baseline: 1.0693x; 1.0039x over previous
#include <cuda_runtime.h>
#include <cstdint>
#include <math.h>

constexpr int B  = 16;
constexpr int C  = 256;
constexpr int HW = 4096;
constexpr int D  = 32;

constexpr int MT = 64;
constexpr int NT = 32;
constexpr int NTILES = HW / NT;   // 128

__device__ float g_q[B * HW * D];   // [b][n][kperm(d)]       fp32
__device__ float g_k[B * HW * D];   // [b][m][d]              fp32 plain
__device__ float g_v[B * HW * C];   // [b][tile][e][kperm(k)] tf32-rounded, tile-major

// cvt.rna.tf32.f32: destination is a .b32 register (tf32 bit pattern).
__device__ __forceinline__ uint32_t to_tf32_bits(float x) {
    uint32_t r;
    asm("cvt.rna.tf32.f32 %0, %1;" : "=r"(r) : "f"(x));
    return r;
}

// tf32 mma: A/B fragments are .b32 regs, C/D are .f32
__device__ __forceinline__ void mma_tf32_16x8x8(
    float& c0, float& c1, float& c2, float& c3,
    uint32_t a0, uint32_t a1, uint32_t a2, uint32_t a3,
    uint32_t b0, uint32_t b1)
{
    asm volatile(
        "mma.sync.aligned.m16n8k8.row.col.f32.tf32.tf32.f32 "
        "{%0,%1,%2,%3}, {%4,%5,%6,%7}, {%8,%9}, {%0,%1,%2,%3};"
        : "+f"(c0), "+f"(c1), "+f"(c2), "+f"(c3)
        : "r"(a0), "r"(a1), "r"(a2), "r"(a3), "r"(b0), "r"(b1));
}

__device__ __forceinline__ uint32_t smem_u32(const void* p) {
    uint32_t a;
    asm("{ .reg .u64 t; cvta.to.shared.u64 t, %1; cvt.u32.u64 %0, t; }"
        : "=r"(a) : "l"(p));
    return a;
}
#define CP_ASYNC8(dst, src) \
    asm volatile("cp.async.ca.shared.global [%0], [%1], 8;" :: "r"(dst), "l"(src))
#define CP_COMMIT() asm volatile("cp.async.commit_group;" ::: "memory")
#define CP_WAIT0()  asm volatile("cp.async.wait_group 0;"  ::: "memory")

// k-interleave within a 32-wide tile (pairs (k, k+4) adjacent) and inverse.
__device__ __forceinline__ int kperm(int k) {
    return ((k & 3) << 3) + ((k >> 3) << 1) + ((k >> 2) & 1);
}
__device__ __forceinline__ int kinv(int d) {
    return (d >> 3) + ((d & 1) << 2) + (((d >> 1) & 3) << 3);
}

// ===========================================================================
// Projection GEMMs (unchanged from round 12)
// ===========================================================================
__global__ __launch_bounds__(256) void proj_kernel(
    const float* __restrict__ x, const float* __restrict__ W,
    float* __restrict__ out, int Etot)
{
    constexpr int BN = 128, KC = 32;
    __shared__ __align__(16) float Xs[KC][BN + 4];
    __shared__ float Ws[KC][33];
    const int b = blockIdx.y, n0 = blockIdx.x * BN, e0 = blockIdx.z * 32;
    const int tid = threadIdx.x, tn = tid & 31, te = tid >> 5;
    float acc[4][4] = {};
    const float* xb = x + (size_t)b * C * HW;
    for (int c0 = 0; c0 < C; c0 += KC) {
        #pragma unroll
        for (int r = 0; r < 4; r++) {
            int idx = tid + 256 * r;
            int c = idx >> 5, n4 = (idx & 31) * 4;
            *(float4*)&Xs[c][n4] = *(const float4*)&xb[(size_t)(c0 + c) * HW + n0 + n4];
        }
        {
            int e = tid >> 3, c4 = (tid & 7) * 4;
            float4 w4 = *(const float4*)&W[(size_t)(e0 + e) * C + c0 + c4];
            Ws[c4 + 0][e] = w4.x; Ws[c4 + 1][e] = w4.y;
            Ws[c4 + 2][e] = w4.z; Ws[c4 + 3][e] = w4.w;
        }
        __syncthreads();
        #pragma unroll
        for (int c = 0; c < KC; c++) {
            float4 xa = *(const float4*)&Xs[c][tn * 4];
            float xv[4] = {xa.x, xa.y, xa.z, xa.w};
            float wb[4];
            #pragma unroll
            for (int j = 0; j < 4; j++) wb[j] = Ws[c][te * 4 + j];
            #pragma unroll
            for (int i = 0; i < 4; i++)
                #pragma unroll
                for (int j = 0; j < 4; j++)
                    acc[i][j] = fmaf(xv[i], wb[j], acc[i][j]);
        }
        __syncthreads();
    }
    #pragma unroll
    for (int i = 0; i < 4; i++) {
        float4 o4 = make_float4(acc[i][0], acc[i][1], acc[i][2], acc[i][3]);
        int n = n0 + tn * 4 + i;
        *(float4*)&out[((size_t)b * HW + n) * Etot + e0 + te * 4] = o4;
    }
}

__global__ __launch_bounds__(256) void proj_kernel_QI(
    const float* __restrict__ x, const float* __restrict__ W,
    float* __restrict__ out)
{
    constexpr int BN = 128, KC = 32;
    __shared__ __align__(16) float Xs[KC][BN + 4];
    __shared__ float Ws[KC][33];
    const int b = blockIdx.y, n0 = blockIdx.x * BN;
    const int tid = threadIdx.x, tn = tid & 31, te = tid >> 5;
    float acc[4][4] = {};
    const float* xb = x + (size_t)b * C * HW;
    for (int c0 = 0; c0 < C; c0 += KC) {
        #pragma unroll
        for (int r = 0; r < 4; r++) {
            int idx = tid + 256 * r;
            int c = idx >> 5, n4 = (idx & 31) * 4;
            *(float4*)&Xs[c][n4] = *(const float4*)&xb[(size_t)(c0 + c) * HW + n0 + n4];
        }
        {
            int e = tid >> 3, c4 = (tid & 7) * 4;
            float4 w4 = *(const float4*)&W[(size_t)e * C + c0 + c4];
            Ws[c4 + 0][e] = w4.x; Ws[c4 + 1][e] = w4.y;
            Ws[c4 + 2][e] = w4.z; Ws[c4 + 3][e] = w4.w;
        }
        __syncthreads();
        #pragma unroll
        for (int c = 0; c < KC; c++) {
            float4 xa = *(const float4*)&Xs[c][tn * 4];
            float xv[4] = {xa.x, xa.y, xa.z, xa.w};
            float wb[4];
            #pragma unroll
            for (int j = 0; j < 4; j++) wb[j] = Ws[c][te * 4 + j];
            #pragma unroll
            for (int i = 0; i < 4; i++)
                #pragma unroll
                for (int j = 0; j < 4; j++)
                    acc[i][j] = fmaf(xv[i], wb[j], acc[i][j]);
        }
        __syncthreads();
    }
    #pragma unroll
    for (int i = 0; i < 4; i++) {
        int n = n0 + tn * 4 + i;
        float* orow = &out[((size_t)b * HW + n) * 32];
        #pragma unroll
        for (int j = 0; j < 4; j++)
            orow[kperm(te * 4 + j)] = acc[i][j];
    }
}

__global__ __launch_bounds__(256) void proj_kernel_T(
    const float* __restrict__ x, const float* __restrict__ W,
    float* __restrict__ out, int Etot)
{
    constexpr int BN = 128, KC = 32;
    __shared__ __align__(16) float Xs[KC][BN + 4];
    __shared__ float Ws[KC][33];
    const int b = blockIdx.y, n0 = blockIdx.x * BN, e0 = blockIdx.z * 32;
    const int tid = threadIdx.x, tn = tid & 31, te = tid >> 5;
    float acc[4][4] = {};
    const float* xb = x + (size_t)b * C * HW;
    for (int c0 = 0; c0 < C; c0 += KC) {
        #pragma unroll
        for (int r = 0; r < 4; r++) {
            int idx = tid + 256 * r;
            int c = idx >> 5, n4 = (idx & 31) * 4;
            *(float4*)&Xs[c][n4] = *(const float4*)&xb[(size_t)(c0 + c) * HW + n0 + n4];
        }
        {
            int e = tid >> 3, c4 = (tid & 7) * 4;
            float4 w4 = *(const float4*)&W[(size_t)(e0 + e) * C + c0 + c4];
            Ws[c4 + 0][e] = w4.x; Ws[c4 + 1][e] = w4.y;
            Ws[c4 + 2][e] = w4.z; Ws[c4 + 3][e] = w4.w;
        }
        __syncthreads();
        #pragma unroll
        for (int c = 0; c < KC; c++) {
            float4 xa = *(const float4*)&Xs[c][tn * 4];
            float xv[4] = {xa.x, xa.y, xa.z, xa.w};
            float wb[4];
            #pragma unroll
            for (int j = 0; j < 4; j++) wb[j] = Ws[c][te * 4 + j];
            #pragma unroll
            for (int i = 0; i < 4; i++)
                #pragma unroll
                for (int j = 0; j < 4; j++)
                    acc[i][j] = fmaf(xv[i], wb[j], acc[i][j]);
        }
        __syncthreads();
    }
    #pragma unroll
    for (int j = 0; j < 4; j++) {
        *(float4*)&Xs[te * 4 + j][tn * 4] = make_float4(
            __uint_as_float(to_tf32_bits(acc[0][j])),
            __uint_as_float(to_tf32_bits(acc[1][j])),
            __uint_as_float(to_tf32_bits(acc[2][j])),
            __uint_as_float(to_tf32_bits(acc[3][j])));
    }
    __syncthreads();
    const int e_loc = tid >> 3;
    const int dbase = (tid & 7) * 4;
    const int t0 = n0 / 32;
    #pragma unroll
    for (int blk = 0; blk < 4; blk++) {
        const float* srow = &Xs[e_loc][blk * 32];
        float4 o;
        o.x = srow[kinv(dbase + 0)];
        o.y = srow[kinv(dbase + 1)];
        o.z = srow[kinv(dbase + 2)];
        o.w = srow[kinv(dbase + 3)];
        *(float4*)&out[(((size_t)b * NTILES + t0 + blk) * C + e0 + e_loc) * 32 + dbase] = o;
    }
}

// ===========================================================================
// Flash attention, occupancy-restructured:
//   CTA = 64m x 128e (grid z = e-half), 3 CTAs/SM target.
//   S on TC (2-term split-tf32, duplicated across e-half twins).
//   PV warp tile 32m x 32e (acc = 32 regs). cp.async V/q prefetch (no rv regs).
// ===========================================================================
constexpr int ST_PV  = 34;   // q/Ps/Vs row stride (floats); 8B-aligned rows
constexpr int ST_STG = 130;  // epilogue stage stride

constexpr int Q_STRIDE  = 32 * ST_PV;    // 1088
constexpr int PS_STRIDE = 64 * ST_PV;    // 2176
constexpr int VS_STRIDE = 128 * ST_PV;   // 4352  (128 e-rows per CTA now)

constexpr int QS_OFF  = 0;                        // 2 x [32][34]
constexpr int PS_OFF  = QS_OFF + 2 * Q_STRIDE;    // 2 x [64][34]
constexpr int INV_OFF = PS_OFF + 2 * PS_STRIDE;   // [64]
constexpr int VS_OFF  = INV_OFF + 64;             // 2 x [128][34] (Stage [64][130] overlays)
constexpr int FLASH_FLOATS = VS_OFF + 2 * VS_STRIDE;   // 15296
constexpr int FLASH_SMEM = FLASH_FLOATS * 4;           // 61184 B

__global__ __launch_bounds__(256, 3) void flash_kernel(
    const float* __restrict__ x, const float* __restrict__ gamma_p,
    float* __restrict__ out)
{
    extern __shared__ __align__(16) float sm[];
    float* Qsm   = sm + QS_OFF;
    float* Ps    = sm + PS_OFF;
    float* invs  = sm + INV_OFF;
    float* Vs    = sm + VS_OFF;
    float* Stage = sm + VS_OFF;   // reused in epilogue

    const int tid  = threadIdx.x;
    const int wid  = tid >> 5;
    const int lane = tid & 31;
    const int b    = blockIdx.y;
    const int m0   = blockIdx.x * MT;
    const int ehalf = blockIdx.z;          // 0 or 1: e range [ehalf*128, +128)

    const int g  = lane >> 2;
    const int tg = lane & 3;
    const int pm = (wid & 1) * 32;   // PV m-block (32 m)
    const int pe = (wid >> 1) * 32;  // PV e-block (32 e of the CTA's 128)
    const int mbW = wid & 3;         // S m16-block
    const int nb0 = (wid >> 2) * 2;  // S n8-blocks

    if (tid < 64) invs[tid] = 0.0f;

    // Kernel-lifetime K hi-fragments for S m-block mbW (2-term split).
    uint32_t Ah[4][4];
    {
        const float* kb = g_k + ((size_t)b * HW + m0 + mbW * 16) * D;
        #pragma unroll
        for (int kk = 0; kk < 4; kk++) {
            Ah[kk][0] = to_tf32_bits(kb[g * D + kk * 8 + tg]);
            Ah[kk][1] = to_tf32_bits(kb[(g + 8) * D + kk * 8 + tg]);
            Ah[kk][2] = to_tf32_bits(kb[g * D + kk * 8 + tg + 4]);
            Ah[kk][3] = to_tf32_bits(kb[(g + 8) * D + kk * 8 + tg + 4]);
        }
    }

    float acc[2][4][4] = {};          // 32m x 32e accumulator (32 regs)
    float rs0 = 0.0f, rs1 = 0.0f;

    const int ldn  = tid >> 3;        // 0..31
    const int ldd4 = (tid & 7) * 4;

    const float* qptr = g_q + ((size_t)b * HW + ldn) * D + ldd4;
    const float* vptr = g_v + (((size_t)b * NTILES) * C + ehalf * 128 + ldn) * 32 + ldd4;

    // Precomputed cp.async smem byte addresses (per-thread)
    const uint32_t sb    = smem_u32(sm);
    const uint32_t qdst0 = sb + (QS_OFF + ldn * ST_PV + ldd4) * 4;
    const uint32_t vdst0 = sb + (VS_OFF + ldn * ST_PV + ldd4) * 4;

    auto load_tile_async = [&](int bufsel) {
        uint32_t qd = qdst0 + bufsel * (Q_STRIDE * 4);
        CP_ASYNC8(qd,     qptr);
        CP_ASYNC8(qd + 8, qptr + 2);
        uint32_t vd = vdst0 + bufsel * (VS_STRIDE * 4);
        #pragma unroll
        for (int p = 0; p < 4; p++) {
            uint32_t d = vd + p * (32 * ST_PV * 4);
            const float* s = vptr + p * 1024;      // 32 e-rows * 32 floats
            CP_ASYNC8(d,     s);
            CP_ASYNC8(d + 8, s + 2);
        }
        CP_COMMIT();
        qptr += NT * D;     // 1024 floats
        vptr += C * 32;     // 8192 floats (next tile block)
    };

    // S phase on tensor cores, 2-term split-tf32 (identical math to round 12).
    auto s_phase = [&](int bufsel) {
        const float* Qb = Qsm + bufsel * Q_STRIDE;
        float* Pb = Ps + bufsel * PS_STRIDE;
        #pragma unroll
        for (int nt = 0; nt < 2; nt++) {
            const int nb = nb0 + nt;
            float sC[4] = {0.f, 0.f, 0.f, 0.f};
            const float* pQ = Qb + (nb * 8 + g) * ST_PV + 8 * tg;
            #pragma unroll
            for (int kk = 0; kk < 4; kk++) {
                float2 qf = *(const float2*)&pQ[2 * kk];
                uint32_t bh0 = to_tf32_bits(qf.x);
                uint32_t bh1 = to_tf32_bits(qf.y);
                uint32_t bl0 = to_tf32_bits(qf.x - __uint_as_float(bh0));
                uint32_t bl1 = to_tf32_bits(qf.y - __uint_as_float(bh1));
                mma_tf32_16x8x8(sC[0], sC[1], sC[2], sC[3],
                                Ah[kk][0], Ah[kk][1], Ah[kk][2], Ah[kk][3],
                                bh0, bh1);
                mma_tf32_16x8x8(sC[0], sC[1], sC[2], sC[3],
                                Ah[kk][0], Ah[kk][1], Ah[kk][2], Ah[kk][3],
                                bl0, bl1);
            }
            const int fl = 16 * (tg & 1) + 2 * nb + (tg >> 1);
            float p0 = __uint_as_float(to_tf32_bits(__expf(sC[0])));
            float p1 = __uint_as_float(to_tf32_bits(__expf(sC[1])));
            float p2 = __uint_as_float(to_tf32_bits(__expf(sC[2])));
            float p3 = __uint_as_float(to_tf32_bits(__expf(sC[3])));
            const int r0 = mbW * 16 + g;
            Pb[r0 * ST_PV + fl]           = p0;
            Pb[r0 * ST_PV + fl + 8]       = p1;
            Pb[(r0 + 8) * ST_PV + fl]     = p2;
            Pb[(r0 + 8) * ST_PV + fl + 8] = p3;
            rs0 += p0 + p1;
            rs1 += p2 + p3;
        }
    };

    // Prologue: tile 0 copied + scored; tile 1 copy in flight.
    load_tile_async(0);
    CP_WAIT0();
    __syncthreads();
    s_phase(0);
    load_tile_async(1);

    for (int t = 0; t < NTILES; t++) {
        const int buf = t & 1, nxt = buf ^ 1;
        if (t + 1 < NTILES) CP_WAIT0();   // tile t+1 landed (thread-local)
        __syncthreads();   // BAR A: tile t+1 CTA-visible; Ps(t) ready

        // PV(t): acc[32m x 32e] += P(t) * V(t)
        {
            const float* pA = Ps + buf * PS_STRIDE + (pm + g) * ST_PV + 8 * tg;
            const float* pB = Vs + buf * VS_STRIDE + (pe + g) * ST_PV + 8 * tg;
            #pragma unroll
            for (int kk = 0; kk < 4; kk++) {
                float2 a00 = *(const float2*)&pA[2 * kk];
                float2 a01 = *(const float2*)&pA[8 * ST_PV + 2 * kk];
                float2 a10 = *(const float2*)&pA[16 * ST_PV + 2 * kk];
                float2 a11 = *(const float2*)&pA[24 * ST_PV + 2 * kk];
                #pragma unroll
                for (int nb = 0; nb < 4; nb++) {
                    float2 bb = *(const float2*)&pB[nb * 8 * ST_PV + 2 * kk];
                    uint32_t b0 = __float_as_uint(bb.x);
                    uint32_t b1 = __float_as_uint(bb.y);
                    mma_tf32_16x8x8(acc[0][nb][0], acc[0][nb][1],
                                    acc[0][nb][2], acc[0][nb][3],
                                    __float_as_uint(a00.x), __float_as_uint(a01.x),
                                    __float_as_uint(a00.y), __float_as_uint(a01.y),
                                    b0, b1);
                    mma_tf32_16x8x8(acc[1][nb][0], acc[1][nb][1],
                                    acc[1][nb][2], acc[1][nb][3],
                                    __float_as_uint(a10.x), __float_as_uint(a11.x),
                                    __float_as_uint(a10.y), __float_as_uint(a11.y),
                                    b0, b1);
                }
            }
        }
        if (t + 1 < NTILES) s_phase(nxt);   // S(t+1) overlaps PV(t)
        __syncthreads();   // BAR B: Vs/Qsm[buf] free for tile t+2 copy
        if (t + 2 < NTILES) load_tile_async(buf);
    }

    // Combine rsum partials (quad-lane shfl + smem atomics).
    rs0 += __shfl_xor_sync(0xffffffffu, rs0, 1);
    rs0 += __shfl_xor_sync(0xffffffffu, rs0, 2);
    rs1 += __shfl_xor_sync(0xffffffffu, rs1, 1);
    rs1 += __shfl_xor_sync(0xffffffffu, rs1, 2);
    if (tg == 0) {
        atomicAdd(&invs[mbW * 16 + g], rs0);
        atomicAdd(&invs[mbW * 16 + 8 + g], rs1);
    }
    __syncthreads();
    const float gamma = *gamma_p;
    if (tid < 64) invs[tid] = gamma / invs[tid];
    __syncthreads();

    // Epilogue: stage [64][130] (covers this CTA's 128 e), coalesced stores.
    {
        #pragma unroll
        for (int mb = 0; mb < 2; mb++) {
            const int r0 = pm + mb * 16 + g;
            const int r1 = r0 + 8;
            const float i0 = invs[r0];
            const float i1 = invs[r1];
            #pragma unroll
            for (int nb = 0; nb < 4; nb++) {
                int col = pe + nb * 8 + tg * 2;
                *(float2*)&Stage[r0 * ST_STG + col] =
                    make_float2(acc[mb][nb][0] * i0, acc[mb][nb][1] * i0);
                *(float2*)&Stage[r1 * ST_STG + col] =
                    make_float2(acc[mb][nb][2] * i1, acc[mb][nb][3] * i1);
            }
        }
        __syncthreads();
        const int ml  = (lane & 15) * 4;
        const int sub = lane >> 4;
        #pragma unroll
        for (int it = 0; it < 8; it++) {
            int e_loc = it * 16 + wid * 2 + sub;
            int eg = ehalf * 128 + e_loc;
            size_t idx = ((size_t)b * C + eg) * HW + m0 + ml;
            float4 xv = *(const float4*)&x[idx];
            float4 ov;
            ov.x = Stage[(ml + 0) * ST_STG + e_loc] + xv.x;
            ov.y = Stage[(ml + 1) * ST_STG + e_loc] + xv.y;
            ov.z = Stage[(ml + 2) * ST_STG + e_loc] + xv.z;
            ov.w = Stage[(ml + 3) * ST_STG + e_loc] + xv.w;
            *(float4*)&out[idx] = ov;
        }
    }
}

// ===========================================================================
extern "C" void kernel_launch(void* const* d_in, const int* in_sizes, int n_in,
                              void* d_out, int out_size)
{
    const float* x     = (const float*)d_in[0];
    const float* Wq    = (const float*)d_in[1];
    const float* Wk    = (const float*)d_in[2];
    const float* Wv    = (const float*)d_in[3];
    const float* gamma = (const float*)d_in[4];
    float* out = (float*)d_out;

    void *qp, *kp, *vp;
    cudaGetSymbolAddress(&qp, g_q);
    cudaGetSymbolAddress(&kp, g_k);
    cudaGetSymbolAddress(&vp, g_v);

    static bool attr_set = false;
    if (!attr_set) {
        cudaFuncSetAttribute(flash_kernel,
                             cudaFuncAttributeMaxDynamicSharedMemorySize,
                             FLASH_SMEM);
        attr_set = true;
    }

    dim3 blk(256);
    proj_kernel_QI<<<dim3(HW / 128, B, 1), blk>>>(x, Wq, (float*)qp);
    proj_kernel   <<<dim3(HW / 128, B, 1), blk>>>(x, Wk, (float*)kp, D);
    proj_kernel_T <<<dim3(HW / 128, B, 8), blk>>>(x, Wv, (float*)vp, C);
    flash_kernel<<<dim3(HW / MT, B, 2), blk, FLASH_SMEM>>>(x, gamma, out);
}